// round 4
// baseline (speedup 1.0000x reference)
#include <cuda_runtime.h>
#include <math.h>

#define TT 512
#define BB 128
#define HH 512
#define NZ 2048
#define TB 65536

// ---------------- static device scratch ----------------
__device__ float g_zx[(size_t)TB*NZ];          // Zx (and pre-GEMM scratch)
__device__ float g_hpre[(size_t)TB*HH];
__device__ float g_ys0[(size_t)TB*HH];
__device__ float g_Whp[2][(size_t)NZ*HH];      // packed Wh^T: [newcol][k]
__device__ float g_hbuf[2][BB*HH];
__device__ unsigned g_cnt, g_gen;
__device__ int g_rmode;

__device__ __forceinline__ float tf(float x){
  unsigned u; asm("cvt.rna.tf32.f32 %0,%1;" : "=r"(u) : "f"(x));
  return __uint_as_float(u);
}
__device__ __forceinline__ void mma8(float* c, const unsigned* a, const unsigned* b){
  asm volatile("mma.sync.aligned.m16n8k8.row.col.f32.tf32.tf32.f32 "
    "{%0,%1,%2,%3},{%4,%5,%6,%7},{%8,%9},{%0,%1,%2,%3};"
    : "+f"(c[0]),"+f"(c[1]),"+f"(c[2]),"+f"(c[3])
    : "r"(a[0]),"r"(a[1]),"r"(a[2]),"r"(a[3]),"r"(b[0]),"r"(b[1]));
}

// ---------------- resets dtype detector (bool->u8 / i32 / f32) ------------
__global__ void detect_resets(const unsigned char* p){
  __shared__ int cF, c1;
  if (threadIdx.x == 0){ cF = 0; c1 = 0; }
  __syncthreads();
  for (int i = threadIdx.x; i < 65536; i += 256){
    unsigned char v = p[i];
    if (v == 0x3f || v == 0x80) atomicAdd(&cF, 1);
    else if (v == 1 && (i & 3)) atomicAdd(&c1, 1);
  }
  __syncthreads();
  if (threadIdx.x == 0) g_rmode = cF ? 2 : (c1 ? 1 : 0);
}

// pack Wh[512][2048] -> Whp[nc][512], nc groups the 64 z-cols each rec CTA owns
__global__ void pack_wh(const float* __restrict__ Wh, int L){
  for (size_t idx = blockIdx.x*blockDim.x + threadIdx.x; idx < (size_t)HH*NZ;
       idx += (size_t)gridDim.x*blockDim.x){
    int k = idx >> 11, j = idx & (NZ-1);
    int g = j >> 9, r = j & 511;
    int nc = ((r >> 4) << 6) + (g << 4) + (r & 15);
    g_Whp[L][(size_t)nc*HH + k] = tf(Wh[idx]);
  }
}

__global__ void init_rec(const float* __restrict__ carryH){
  int i = blockIdx.x*blockDim.x + threadIdx.x;
  if (i < BB*HH) g_hbuf[0][i] = tf(carryH[i]);
  if (i == 0){ g_cnt = 0u; g_gen = 0u; }
}

// ---------------- bulk tf32 GEMM: C[TBxN] = A[TBx512]@B[512xN]+bias --------
template<bool RELU>
__global__ __launch_bounds__(256) void gemm_tf32(
    const float* __restrict__ Aext, int aSel,
    const float* __restrict__ B, const float* __restrict__ bias,
    int cSel, int N)
{
  __shared__ float As[128][36];
  __shared__ float Bs[128][36];  // [n][k]
  const float* A = (aSel == 1) ? g_hpre : (aSel == 2) ? g_ys0 : Aext;
  float* C = (cSel == 1) ? g_hpre : g_zx;
  const int mt = blockIdx.y, nt = blockIdx.x, tid = threadIdx.x;
  const int wid = tid >> 5, lane = tid & 31, gID = lane >> 2, tig = lane & 3;
  const int wM = wid >> 1, wN = wid & 1;

  float acc[2][8][4];
  #pragma unroll
  for (int mi = 0; mi < 2; mi++)
    #pragma unroll
    for (int ni = 0; ni < 8; ni++)
      #pragma unroll
      for (int q = 0; q < 4; q++) acc[mi][ni][q] = 0.f;

  for (int kt = 0; kt < 512; kt += 32){
    #pragma unroll
    for (int i = 0; i < 4; i++){
      int idx = tid + i*256, r = idx >> 3, c4 = (idx & 7)*4;
      float4 v = *(const float4*)&A[(size_t)(mt*128 + r)*512 + kt + c4];
      As[r][c4] = tf(v.x); As[r][c4+1] = tf(v.y);
      As[r][c4+2] = tf(v.z); As[r][c4+3] = tf(v.w);
    }
    #pragma unroll
    for (int i = 0; i < 4; i++){
      int idx = tid + i*256, k = idx >> 5, n4 = (idx & 31)*4;
      float4 v = *(const float4*)&B[(size_t)(kt + k)*N + nt*128 + n4];
      Bs[n4][k] = tf(v.x); Bs[n4+1][k] = tf(v.y);
      Bs[n4+2][k] = tf(v.z); Bs[n4+3][k] = tf(v.w);
    }
    __syncthreads();
    #pragma unroll
    for (int kk = 0; kk < 32; kk += 8){
      unsigned a[2][4], b[8][2];
      #pragma unroll
      for (int mi = 0; mi < 2; mi++){
        int r0 = wM*32 + mi*16 + gID;
        a[mi][0] = __float_as_uint(As[r0][kk+tig]);
        a[mi][1] = __float_as_uint(As[r0+8][kk+tig]);
        a[mi][2] = __float_as_uint(As[r0][kk+4+tig]);
        a[mi][3] = __float_as_uint(As[r0+8][kk+4+tig]);
      }
      #pragma unroll
      for (int ni = 0; ni < 8; ni++){
        int n0 = wN*64 + ni*8 + gID;
        b[ni][0] = __float_as_uint(Bs[n0][kk+tig]);
        b[ni][1] = __float_as_uint(Bs[n0][kk+4+tig]);
      }
      #pragma unroll
      for (int mi = 0; mi < 2; mi++)
        #pragma unroll
        for (int ni = 0; ni < 8; ni++)
          mma8(acc[mi][ni], a[mi], b[ni]);
    }
    __syncthreads();
  }
  #pragma unroll
  for (int mi = 0; mi < 2; mi++){
    int r0 = mt*128 + wM*32 + mi*16 + gID;
    #pragma unroll
    for (int ni = 0; ni < 8; ni++){
      int col = nt*128 + wN*64 + ni*8 + tig*2;
      float b0 = bias[col], b1 = bias[col+1];
      float v0 = acc[mi][ni][0]+b0, v1 = acc[mi][ni][1]+b1;
      float v2 = acc[mi][ni][2]+b0, v3 = acc[mi][ni][3]+b1;
      if (RELU){ v0=fmaxf(v0,0.f); v1=fmaxf(v1,0.f); v2=fmaxf(v2,0.f); v3=fmaxf(v3,0.f); }
      *(float2*)&C[(size_t)r0*N + col]     = make_float2(v0, v1);
      *(float2*)&C[(size_t)(r0+8)*N + col] = make_float2(v2, v3);
    }
  }
}

// ---------------- LayerNorm + ReLU: g_zx[:,512] -> g_hpre ------------------
__global__ __launch_bounds__(256) void ln_relu(
    const float* __restrict__ sc, const float* __restrict__ bi)
{
  int row = blockIdx.x*8 + (threadIdx.x >> 5), lane = threadIdx.x & 31;
  float v[16], s = 0.f, s2 = 0.f;
  #pragma unroll
  for (int j = 0; j < 16; j++){
    v[j] = g_zx[(size_t)row*512 + lane + j*32];
    s += v[j]; s2 += v[j]*v[j];
  }
  #pragma unroll
  for (int o = 16; o; o >>= 1){
    s  += __shfl_xor_sync(0xffffffffu, s,  o);
    s2 += __shfl_xor_sync(0xffffffffu, s2, o);
  }
  float mu = s*(1.f/512.f);
  float var = fmaxf(s2*(1.f/512.f) - mu*mu, 0.f);
  float rs = rsqrtf(var + 1e-6f);
  #pragma unroll
  for (int j = 0; j < 16; j++){
    int col = lane + j*32;
    g_hpre[(size_t)row*512 + col] = fmaxf((v[j]-mu)*rs*sc[col] + bi[col], 0.f);
  }
}

// ---------------- persistent LSTM layer ----------------
#define RECSMEM ((64*516 + 32*516 + 32*68)*4)

__device__ __forceinline__ void gbar(){
  __syncthreads();
  if (threadIdx.x == 0){
    __threadfence();
    unsigned g = ((volatile unsigned*)&g_gen)[0];
    if (atomicAdd(&g_cnt, 1u) == 127u){
      g_cnt = 0u; __threadfence(); atomicAdd(&g_gen, 1u);
    } else {
      while (((volatile unsigned*)&g_gen)[0] == g) { }
    }
  }
  __syncthreads();
}

__global__ __launch_bounds__(256,1) void rec_lstm(
    int L, const float* __restrict__ carryC, const void* __restrict__ resets,
    float* __restrict__ ysExt, float* __restrict__ coutP, float* __restrict__ houtP)
{
  extern __shared__ float sm[];
  float* Bs = sm;                    // [64][516]
  float* As = sm + 64*516;           // [32][516]
  float* Zs = sm + 96*516;           // [32][68]
  __shared__ int s_rst[32];

  const float* Whp = g_Whp[L];
  float* ys = ysExt ? ysExt : g_ys0;
  const int tid = threadIdx.x, cta = blockIdx.x;
  const int mbase = (cta >> 5)*32, ni = cta & 31, nbase = ni*64;
  const int wid = tid >> 5, lane = tid & 31, gID = lane >> 2, tig = lane & 3;
  const int wM = wid >> 2, wN = wid & 3;
  const int mode = g_rmode;

  for (int idx = tid; idx < 64*128; idx += 256){
    int n = idx >> 7, k4 = (idx & 127)*4;
    *(float4*)&Bs[n*516 + k4] = *(const float4*)&Whp[(size_t)(nbase+n)*512 + k4];
  }
  float cst[2];
  #pragma unroll
  for (int pi = 0; pi < 2; pi++){
    int p = tid + pi*256, r = p >> 4, c = p & 15;
    cst[pi] = carryC[(size_t)(mbase+r)*512 + ni*16 + c];
  }

  for (int t = 0; t < TT; t++){
    const float* hb = g_hbuf[t & 1];
    float* hn = g_hbuf[(t & 1) ^ 1];
    if (tid < 32){
      int ir = t*128 + mbase + tid;
      bool z;
      if (mode == 1)      z = ((const unsigned char*)resets)[ir] != 0;
      else if (mode == 2) z = ((const float*)resets)[ir] != 0.f;
      else                z = ((const int*)resets)[ir] != 0;
      s_rst[tid] = z ? 1 : 0;
    }
    __syncthreads();
    for (int idx = tid; idx < 32*128; idx += 256){
      int r = idx >> 7, c4 = (idx & 127)*4;
      float4 v = __ldcg((const float4*)&hb[(mbase+r)*512 + c4]);
      if (s_rst[r]) v = make_float4(0.f, 0.f, 0.f, 0.f);
      *(float4*)&As[r*516 + c4] = v;
    }
    __syncthreads();

    float acc[2][4] = {{0.f,0.f,0.f,0.f},{0.f,0.f,0.f,0.f}};
    #pragma unroll 4
    for (int kk = 0; kk < 512; kk += 8){
      unsigned a[4];
      int r0 = (wM*16 + gID)*516;
      a[0] = __float_as_uint(As[r0 + kk + tig]);
      a[1] = __float_as_uint(As[r0 + 8*516 + kk + tig]);
      a[2] = __float_as_uint(As[r0 + kk + 4 + tig]);
      a[3] = __float_as_uint(As[r0 + 8*516 + kk + 4 + tig]);
      #pragma unroll
      for (int nt = 0; nt < 2; nt++){
        unsigned b[2];
        int n0 = (wN*16 + nt*8 + gID)*516;
        b[0] = __float_as_uint(Bs[n0 + kk + tig]);
        b[1] = __float_as_uint(Bs[n0 + kk + 4 + tig]);
        mma8(acc[nt], a, b);
      }
    }
    {
      int zr = wM*16 + gID, zc = wN*16;
      #pragma unroll
      for (int nt = 0; nt < 2; nt++){
        Zs[zr*68 + zc + nt*8 + tig*2]       = acc[nt][0];
        Zs[zr*68 + zc + nt*8 + tig*2 + 1]   = acc[nt][1];
        Zs[(zr+8)*68 + zc + nt*8 + tig*2]     = acc[nt][2];
        Zs[(zr+8)*68 + zc + nt*8 + tig*2 + 1] = acc[nt][3];
      }
    }
    __syncthreads();

    #pragma unroll
    for (int pi = 0; pi < 2; pi++){
      int p = tid + pi*256, r = p >> 4, c = p & 15;
      size_t rg = (size_t)t*128 + mbase + r;
      const float* zxr = &g_zx[rg*NZ];
      int hcol = ni*16 + c;
      float zi = Zs[r*68 + c]      + zxr[hcol];
      float zf = Zs[r*68 + 16 + c] + zxr[512 + hcol];
      float zg = Zs[r*68 + 32 + c] + zxr[1024 + hcol];
      float zo = Zs[r*68 + 48 + c] + zxr[1536 + hcol];
      float cc = s_rst[r] ? 0.f : cst[pi];
      float ig = 1.f/(1.f + __expf(-zi));
      float fg = 1.f/(1.f + __expf(-zf));
      float og = 1.f/(1.f + __expf(-zo));
      cc = fg*cc + ig*tanhf(zg);
      float nh = og*tanhf(cc);
      cst[pi] = cc;
      __stcg(&hn[(mbase+r)*512 + hcol], tf(nh));
      ys[rg*512 + hcol] = nh;
      if (t == TT-1){
        coutP[(size_t)(mbase+r)*512 + hcol] = cc;
        houtP[(size_t)(mbase+r)*512 + hcol] = nh;
      }
    }
    gbar();
  }
}

// ---------------- logits: g_hpre[TBx512] @ outW[512x20] + outb -------------
__global__ __launch_bounds__(256) void logits_k(
    const float* __restrict__ W, const float* __restrict__ b, float* __restrict__ C)
{
  __shared__ float Ws[512*20];
  int tid = threadIdx.x;
  for (int i = tid; i < 512*20; i += 256) Ws[i] = W[i];
  __syncthreads();
  int row = blockIdx.x*8 + (tid >> 5), lane = tid & 31;
  float acc[20];
  #pragma unroll
  for (int c = 0; c < 20; c++) acc[c] = 0.f;
  #pragma unroll 4
  for (int j = 0; j < 16; j++){
    float a = g_hpre[(size_t)row*512 + lane + j*32];
    const float* w = &Ws[(lane + j*32)*20];
    #pragma unroll
    for (int c = 0; c < 20; c++) acc[c] += a*w[c];
  }
  #pragma unroll
  for (int c = 0; c < 20; c++)
    #pragma unroll
    for (int o = 16; o; o >>= 1) acc[c] += __shfl_xor_sync(0xffffffffu, acc[c], o);
  if (lane < 20) C[(size_t)row*20 + lane] = acc[lane] + b[lane];
}

// ---------------- launcher ----------------
extern "C" void kernel_launch(void* const* d_in, const int*, int, void* d_out_, int){
  const float* x     = (const float*)d_in[0];
  const void*  rsts  = d_in[1];
  const float* cc    = (const float*)d_in[2];
  const float* ch    = (const float*)d_in[3];
  const float* preW  = (const float*)d_in[4];
  const float* preb  = (const float*)d_in[5];
  const float* lns   = (const float*)d_in[6];
  const float* lnb   = (const float*)d_in[7];
  const float* Wi0   = (const float*)d_in[8];
  const float* Wh0   = (const float*)d_in[9];
  const float* b0    = (const float*)d_in[10];
  const float* Wi1   = (const float*)d_in[11];
  const float* Wh1   = (const float*)d_in[12];
  const float* b1    = (const float*)d_in[13];
  const float* postW = (const float*)d_in[14];
  const float* postb = (const float*)d_in[15];
  const float* outW  = (const float*)d_in[16];
  const float* outb  = (const float*)d_in[17];
  float* out = (float*)d_out_;
  const size_t OC = 0, OH = 131072, OL = 262144, OE = 1572864;

  cudaFuncSetAttribute(rec_lstm, cudaFuncAttributeMaxDynamicSharedMemorySize, RECSMEM);

  detect_resets<<<1,256>>>((const unsigned char*)rsts);
  dim3 g512(4,512), g2048(16,512);
  // pre-dense -> g_zx[:,512]
  gemm_tf32<false><<<g512,256>>>(x, 0, preW, preb, 0, 512);
  ln_relu<<<8192,256>>>(lns, lnb);
  // Zx0 = hpre @ Wi0 + b0
  gemm_tf32<false><<<g2048,256>>>(nullptr, 1, Wi0, b0, 0, 2048);
  pack_wh<<<2048,512>>>(Wh0, 0);
  init_rec<<<256,256>>>(ch);
  rec_lstm<<<128,256,RECSMEM>>>(0, cc, rsts, nullptr, out + OC, out + OH);
  // Zx1 = ys0 @ Wi1 + b1
  gemm_tf32<false><<<g2048,256>>>(nullptr, 2, Wi1, b1, 0, 2048);
  pack_wh<<<2048,512>>>(Wh1, 1);
  init_rec<<<256,256>>>(ch + 65536);
  rec_lstm<<<128,256,RECSMEM>>>(1, cc + 65536, rsts, out + OE,
                                out + OC + 65536, out + OH + 65536);
  // post-dense + relu -> g_hpre
  gemm_tf32<true><<<g512,256>>>(out + OE, 0, postW, postb, 1, 512);
  logits_k<<<8192,256>>>(outW, outb, out + OL);
}

// round 5
// speedup vs baseline: 1.2598x; 1.2598x over previous
#include <cuda_runtime.h>
#include <math.h>

#define TT 512
#define BB 128
#define HH 512
#define NZ 2048
#define TB 65536

// ---------------- static device scratch ----------------
__device__ float g_zx[(size_t)TB*NZ];
__device__ float g_hpre[(size_t)TB*HH];
__device__ float g_ys0[(size_t)TB*HH];
__device__ float g_Whp[2][(size_t)NZ*HH];   // swizzled: [(nc*4+k%4)*128 + k/4]
__device__ float g_hbuf[2][BB*HH];          // swizzled: [(row*4+c%4)*128 + c/4]
__device__ unsigned char g_rst[TB];
__device__ unsigned g_cnt, g_gen;
__device__ int g_rmode;

__device__ __forceinline__ float tf(float x){
  unsigned u; asm("cvt.rna.tf32.f32 %0,%1;" : "=r"(u) : "f"(x));
  return __uint_as_float(u);
}
__device__ __forceinline__ unsigned tfu(float x){
  unsigned u; asm("cvt.rna.tf32.f32 %0,%1;" : "=r"(u) : "f"(x));
  return u;
}
__device__ __forceinline__ void mma8(float* c, const unsigned* a, const unsigned* b){
  asm volatile("mma.sync.aligned.m16n8k8.row.col.f32.tf32.tf32.f32 "
    "{%0,%1,%2,%3},{%4,%5,%6,%7},{%8,%9},{%0,%1,%2,%3};"
    : "+f"(c[0]),"+f"(c[1]),"+f"(c[2]),"+f"(c[3])
    : "r"(a[0]),"r"(a[1]),"r"(a[2]),"r"(a[3]),"r"(b[0]),"r"(b[1]));
}
__device__ __forceinline__ void cpa16(void* dst, const void* src){
  unsigned d = (unsigned)__cvta_generic_to_shared(dst);
  asm volatile("cp.async.cg.shared.global [%0], [%1], 16;" :: "r"(d), "l"(src));
}

// ---------------- resets dtype detect + convert ----------------
__global__ void detect_resets(const unsigned char* p){
  __shared__ int cF, c1;
  if (threadIdx.x == 0){ cF = 0; c1 = 0; }
  __syncthreads();
  for (int i = threadIdx.x; i < 65536; i += 256){
    unsigned char v = p[i];
    if (v == 0x3f || v == 0x80) atomicAdd(&cF, 1);
    else if (v == 1 && (i & 3)) atomicAdd(&c1, 1);
  }
  __syncthreads();
  if (threadIdx.x == 0) g_rmode = cF ? 2 : (c1 ? 1 : 0);
}
__global__ void conv_resets(const void* p){
  int i = blockIdx.x*blockDim.x + threadIdx.x;
  int m = g_rmode;
  bool z;
  if (m == 1)      z = ((const unsigned char*)p)[i] != 0;
  else if (m == 2) z = ((const float*)p)[i] != 0.f;
  else             z = ((const int*)p)[i] != 0;
  g_rst[i] = z ? 1 : 0;
}

// pack Wh[512][2048] -> swizzled tf32-rounded layout
__global__ void pack_wh(const float* __restrict__ Wh, int L){
  for (size_t idx = blockIdx.x*blockDim.x + threadIdx.x; idx < (size_t)HH*NZ;
       idx += (size_t)gridDim.x*blockDim.x){
    int k = idx >> 11, j = idx & (NZ-1);
    int g = j >> 9, r = j & 511;
    int nc = ((r >> 4) << 6) + (g << 4) + (r & 15);
    g_Whp[L][(size_t)(nc*4 + (k & 3))*128 + (k >> 2)] = tf(Wh[idx]);
  }
}

__global__ void init_rec(const float* __restrict__ carryH){
  int i = blockIdx.x*blockDim.x + threadIdx.x;
  if (i < BB*HH){
    int row = i >> 9, col = i & 511;
    g_hbuf[0][(row*4 + (col & 3))*128 + (col >> 2)] = tf(carryH[i]);
  }
  if (i == 0){ g_cnt = 0u; g_gen = 0u; }
}

// ---------------- bulk tf32 GEMM (cp.async double-buffered) ----------------
#define GEMM_SMEM ((2*128*36 + 2*32*136)*4)
#define AS(st,r,k) shA[((st)*128+(r))*36 + (k)]
#define BS(st,k,n) shB[((st)*32+(k))*136 + (n)]

template<bool RELU>
__global__ __launch_bounds__(256) void gemm_tf32(
    const float* __restrict__ Aext, int aSel,
    const float* __restrict__ B, const float* __restrict__ bias,
    int cSel, int N)
{
  extern __shared__ float sh[];
  float* shA = sh;
  float* shB = sh + 2*128*36;
  const float* A = (aSel == 1) ? g_hpre : (aSel == 2) ? g_ys0 : Aext;
  float* C = (cSel == 1) ? g_hpre : g_zx;
  const int mt = blockIdx.y, nt = blockIdx.x, tid = threadIdx.x;
  const int wid = tid >> 5, lane = tid & 31, gID = lane >> 2, tig = lane & 3;
  const int wM = wid >> 1, wN = wid & 1;

  float acc[2][8][4];
  #pragma unroll
  for (int mi = 0; mi < 2; mi++)
    #pragma unroll
    for (int ni = 0; ni < 8; ni++)
      #pragma unroll
      for (int q = 0; q < 4; q++) acc[mi][ni][q] = 0.f;

  auto issue = [&](int kt, int st){
    #pragma unroll
    for (int i = 0; i < 4; i++){
      int idx = tid + i*256, r = idx >> 3, c4 = (idx & 7)*4;
      cpa16(&AS(st, r, c4), &A[(size_t)(mt*128 + r)*512 + kt*32 + c4]);
    }
    #pragma unroll
    for (int i = 0; i < 4; i++){
      int idx = tid + i*256, k = idx >> 5, n4 = (idx & 31)*4;
      cpa16(&BS(st, k, n4), &B[(size_t)(kt*32 + k)*N + nt*128 + n4]);
    }
    asm volatile("cp.async.commit_group;" ::: "memory");
  };

  issue(0, 0);
  issue(1, 1);
  for (int kt = 0; kt < 16; kt++){
    if (kt < 15) asm volatile("cp.async.wait_group 1;" ::: "memory");
    else         asm volatile("cp.async.wait_group 0;" ::: "memory");
    __syncthreads();
    int st = kt & 1;
    #pragma unroll
    for (int kk = 0; kk < 32; kk += 8){
      unsigned a[2][4], b[8][2];
      #pragma unroll
      for (int mi = 0; mi < 2; mi++){
        int r0 = wM*32 + mi*16 + gID;
        a[mi][0] = tfu(AS(st, r0,   kk+tig));
        a[mi][1] = tfu(AS(st, r0+8, kk+tig));
        a[mi][2] = tfu(AS(st, r0,   kk+4+tig));
        a[mi][3] = tfu(AS(st, r0+8, kk+4+tig));
      }
      #pragma unroll
      for (int ni = 0; ni < 8; ni++){
        int n0 = wN*64 + ni*8 + gID;
        b[ni][0] = tfu(BS(st, kk+tig,   n0));
        b[ni][1] = tfu(BS(st, kk+4+tig, n0));
      }
      #pragma unroll
      for (int mi = 0; mi < 2; mi++)
        #pragma unroll
        for (int ni = 0; ni < 8; ni++)
          mma8(acc[mi][ni], a[mi], b[ni]);
    }
    __syncthreads();
    if (kt + 2 < 16) issue(kt + 2, st);
  }

  #pragma unroll
  for (int mi = 0; mi < 2; mi++){
    int r0 = mt*128 + wM*32 + mi*16 + gID;
    #pragma unroll
    for (int ni = 0; ni < 8; ni++){
      int col = nt*128 + wN*64 + ni*8 + tig*2;
      float b0 = bias[col], b1 = bias[col+1];
      float v0 = acc[mi][ni][0]+b0, v1 = acc[mi][ni][1]+b1;
      float v2 = acc[mi][ni][2]+b0, v3 = acc[mi][ni][3]+b1;
      if (RELU){ v0=fmaxf(v0,0.f); v1=fmaxf(v1,0.f); v2=fmaxf(v2,0.f); v3=fmaxf(v3,0.f); }
      *(float2*)&C[(size_t)r0*N + col]     = make_float2(v0, v1);
      *(float2*)&C[(size_t)(r0+8)*N + col] = make_float2(v2, v3);
    }
  }
}

// ---------------- LayerNorm + ReLU ----------------
__global__ __launch_bounds__(256) void ln_relu(
    const float* __restrict__ sc, const float* __restrict__ bi)
{
  int row = blockIdx.x*8 + (threadIdx.x >> 5), lane = threadIdx.x & 31;
  float v[16], s = 0.f, s2 = 0.f;
  #pragma unroll
  for (int j = 0; j < 16; j++){
    v[j] = g_zx[(size_t)row*512 + lane + j*32];
    s += v[j]; s2 += v[j]*v[j];
  }
  #pragma unroll
  for (int o = 16; o; o >>= 1){
    s  += __shfl_xor_sync(0xffffffffu, s,  o);
    s2 += __shfl_xor_sync(0xffffffffu, s2, o);
  }
  float mu = s*(1.f/512.f);
  float var = fmaxf(s2*(1.f/512.f) - mu*mu, 0.f);
  float rs = rsqrtf(var + 1e-6f);
  #pragma unroll
  for (int j = 0; j < 16; j++){
    int col = lane + j*32;
    g_hpre[(size_t)row*512 + col] = fmaxf((v[j]-mu)*rs*sc[col] + bi[col], 0.f);
  }
}

// ---------------- persistent LSTM layer ----------------
#define RECSMEM ((256*140 + 128*140 + 32*68)*4)

__device__ __forceinline__ void gbar(){
  __syncthreads();
  if (threadIdx.x == 0){
    __threadfence();
    unsigned g = ((volatile unsigned*)&g_gen)[0];
    if (atomicAdd(&g_cnt, 1u) == 127u){
      g_cnt = 0u; __threadfence(); atomicAdd(&g_gen, 1u);
    } else {
      while (((volatile unsigned*)&g_gen)[0] == g) { }
      __threadfence();
    }
  }
  __syncthreads();
}

__global__ __launch_bounds__(256,1) void rec_lstm(
    int L, const float* __restrict__ carryC,
    float* __restrict__ ysExt, float* __restrict__ coutP, float* __restrict__ houtP)
{
  extern __shared__ float sm[];
  float* Bs2 = sm;                 // [256][140]
  float* As2 = sm + 256*140;       // [128][140]
  float* Zs  = sm + 384*140;       // [32][68]
  __shared__ int s_rst[32];

  const float* Whp = g_Whp[L];
  float* ys = ysExt ? ysExt : g_ys0;
  const int tid = threadIdx.x, cta = blockIdx.x;
  const int mbase = (cta >> 5)*32, ni = cta & 31;
  const int wid = tid >> 5, lane = tid & 31, gID = lane >> 2, tig = lane & 3;
  const int wM = wid >> 2, wN = wid & 3;

  for (int idx = tid; idx < 256*32; idx += 256){
    int r = idx >> 5, j4 = (idx & 31)*4;
    *(float4*)&Bs2[r*140 + j4] =
      *(const float4*)&Whp[(size_t)(ni*256 + r)*128 + j4];
  }
  float cst[2];
  #pragma unroll
  for (int pi = 0; pi < 2; pi++){
    int p = tid + pi*256, r = p >> 4, c = p & 15;
    cst[pi] = carryC[(size_t)(mbase+r)*512 + ni*16 + c];
  }

  const float* pa0 = As2 + ((wM*16 + gID)*4 + tig)*140;
  const float* pa8 = As2 + ((wM*16 + 8 + gID)*4 + tig)*140;
  const float* pb0 = Bs2 + ((wN*16 + gID)*4 + tig)*140;
  const float* pb1 = Bs2 + ((wN*16 + 8 + gID)*4 + tig)*140;

  for (int t = 0; t < TT; t++){
    const float* hb = g_hbuf[t & 1];
    float* hn = g_hbuf[(t & 1) ^ 1];
    // prefetch Zx into registers (hidden behind fill + MMA)
    float pz[2][4];
    #pragma unroll
    for (int pi = 0; pi < 2; pi++){
      int p = tid + pi*256, r = p >> 4, c = p & 15;
      const float* zxr = &g_zx[((size_t)t*128 + mbase + r)*NZ + ni*16 + c];
      pz[pi][0] = __ldg(zxr);
      pz[pi][1] = __ldg(zxr + 512);
      pz[pi][2] = __ldg(zxr + 1024);
      pz[pi][3] = __ldg(zxr + 1536);
    }
    if (tid < 32) s_rst[tid] = g_rst[t*128 + mbase + tid];
    __syncthreads();
    for (int idx = tid; idx < 128*32; idx += 256){
      int r = idx >> 5, j4 = (idx & 31)*4;
      float4 v = __ldcg((const float4*)&hb[(mbase*4 + r)*128 + j4]);
      if (s_rst[r >> 2]){ v.x = 0.f; v.y = 0.f; v.z = 0.f; v.w = 0.f; }
      *(float4*)&As2[r*140 + j4] = v;
    }
    __syncthreads();

    float acc0[4] = {0.f,0.f,0.f,0.f}, acc1[4] = {0.f,0.f,0.f,0.f};
    #pragma unroll 4
    for (int j = 0; j < 128; j += 4){
      float4 a0 = *(const float4*)(pa0 + j), a8 = *(const float4*)(pa8 + j);
      float4 b0 = *(const float4*)(pb0 + j), b1 = *(const float4*)(pb1 + j);
      unsigned A1[4] = {__float_as_uint(a0.x), __float_as_uint(a8.x),
                        __float_as_uint(a0.y), __float_as_uint(a8.y)};
      unsigned Bv[2] = {__float_as_uint(b0.x), __float_as_uint(b0.y)};
      mma8(acc0, A1, Bv);
      unsigned Bw[2] = {__float_as_uint(b1.x), __float_as_uint(b1.y)};
      mma8(acc1, A1, Bw);
      unsigned A2[4] = {__float_as_uint(a0.z), __float_as_uint(a8.z),
                        __float_as_uint(a0.w), __float_as_uint(a8.w)};
      unsigned Bx[2] = {__float_as_uint(b0.z), __float_as_uint(b0.w)};
      mma8(acc0, A2, Bx);
      unsigned By[2] = {__float_as_uint(b1.z), __float_as_uint(b1.w)};
      mma8(acc1, A2, By);
    }
    {
      int zr = wM*16 + gID, zc = wN*16 + tig*2;
      Zs[zr*68 + zc]       = acc0[0]; Zs[zr*68 + zc + 1]       = acc0[1];
      Zs[(zr+8)*68 + zc]   = acc0[2]; Zs[(zr+8)*68 + zc + 1]   = acc0[3];
      Zs[zr*68 + zc + 8]     = acc1[0]; Zs[zr*68 + zc + 9]     = acc1[1];
      Zs[(zr+8)*68 + zc + 8] = acc1[2]; Zs[(zr+8)*68 + zc + 9] = acc1[3];
    }
    __syncthreads();

    #pragma unroll
    for (int pi = 0; pi < 2; pi++){
      int p = tid + pi*256, r = p >> 4, c = p & 15;
      size_t rg = (size_t)t*128 + mbase + r;
      float zi = Zs[r*68 + c]      + pz[pi][0];
      float zf = Zs[r*68 + 16 + c] + pz[pi][1];
      float zg = Zs[r*68 + 32 + c] + pz[pi][2];
      float zo = Zs[r*68 + 48 + c] + pz[pi][3];
      float cc = s_rst[r] ? 0.f : cst[pi];
      float ig = 1.f/(1.f + __expf(-zi));
      float fg = 1.f/(1.f + __expf(-zf));
      float og = 1.f/(1.f + __expf(-zo));
      cc = fg*cc + ig*tanhf(zg);
      float nh = og*tanhf(cc);
      cst[pi] = cc;
      int hcol = ni*16 + c;
      __stcg(&hn[((mbase+r)*4 + (c & 3))*128 + ni*4 + (c >> 2)], tf(nh));
      ys[rg*512 + hcol] = nh;
      if (t == TT-1){
        coutP[(size_t)(mbase+r)*512 + hcol] = cc;
        houtP[(size_t)(mbase+r)*512 + hcol] = nh;
      }
    }
    gbar();
  }
}

// ---------------- logits ----------------
__global__ __launch_bounds__(256) void logits_k(
    const float* __restrict__ W, const float* __restrict__ b, float* __restrict__ C)
{
  __shared__ float Ws[512*20];
  int tid = threadIdx.x;
  for (int i = tid; i < 512*20; i += 256) Ws[i] = W[i];
  __syncthreads();
  int row = blockIdx.x*8 + (tid >> 5), lane = tid & 31;
  float acc[20];
  #pragma unroll
  for (int c = 0; c < 20; c++) acc[c] = 0.f;
  #pragma unroll 4
  for (int j = 0; j < 16; j++){
    float a = g_hpre[(size_t)row*512 + lane + j*32];
    const float* w = &Ws[(lane + j*32)*20];
    #pragma unroll
    for (int c = 0; c < 20; c++) acc[c] += a*w[c];
  }
  #pragma unroll
  for (int c = 0; c < 20; c++)
    #pragma unroll
    for (int o = 16; o; o >>= 1) acc[c] += __shfl_xor_sync(0xffffffffu, acc[c], o);
  if (lane < 20) C[(size_t)row*20 + lane] = acc[lane] + b[lane];
}

// ---------------- launcher ----------------
extern "C" void kernel_launch(void* const* d_in, const int*, int, void* d_out_, int){
  const float* x     = (const float*)d_in[0];
  const void*  rsts  = d_in[1];
  const float* cc    = (const float*)d_in[2];
  const float* ch    = (const float*)d_in[3];
  const float* preW  = (const float*)d_in[4];
  const float* preb  = (const float*)d_in[5];
  const float* lns   = (const float*)d_in[6];
  const float* lnb   = (const float*)d_in[7];
  const float* Wi0   = (const float*)d_in[8];
  const float* Wh0   = (const float*)d_in[9];
  const float* b0    = (const float*)d_in[10];
  const float* Wi1   = (const float*)d_in[11];
  const float* Wh1   = (const float*)d_in[12];
  const float* b1    = (const float*)d_in[13];
  const float* postW = (const float*)d_in[14];
  const float* postb = (const float*)d_in[15];
  const float* outW  = (const float*)d_in[16];
  const float* outb  = (const float*)d_in[17];
  float* out = (float*)d_out_;
  const size_t OC = 0, OH = 131072, OL = 262144, OE = 1572864;

  cudaFuncSetAttribute(gemm_tf32<false>, cudaFuncAttributeMaxDynamicSharedMemorySize, GEMM_SMEM);
  cudaFuncSetAttribute(gemm_tf32<true>,  cudaFuncAttributeMaxDynamicSharedMemorySize, GEMM_SMEM);
  cudaFuncSetAttribute(rec_lstm, cudaFuncAttributeMaxDynamicSharedMemorySize, RECSMEM);

  detect_resets<<<1,256>>>((const unsigned char*)rsts);
  conv_resets<<<256,256>>>(rsts);
  dim3 g512(4,512), g2048(16,512);
  gemm_tf32<false><<<g512,256,GEMM_SMEM>>>(x, 0, preW, preb, 0, 512);
  ln_relu<<<8192,256>>>(lns, lnb);
  gemm_tf32<false><<<g2048,256,GEMM_SMEM>>>(nullptr, 1, Wi0, b0, 0, 2048);
  pack_wh<<<2048,512>>>(Wh0, 0);
  init_rec<<<256,256>>>(ch);
  rec_lstm<<<128,256,RECSMEM>>>(0, cc, nullptr, out + OC, out + OH);
  gemm_tf32<false><<<g2048,256,GEMM_SMEM>>>(nullptr, 2, Wi1, b1, 0, 2048);
  pack_wh<<<2048,512>>>(Wh1, 1);
  init_rec<<<256,256>>>(ch + 65536);
  rec_lstm<<<128,256,RECSMEM>>>(1, cc + 65536, out + OE,
                                out + OC + 65536, out + OH + 65536);
  gemm_tf32<true><<<g512,256,GEMM_SMEM>>>(out + OE, 0, postW, postb, 1, 512);
  logits_k<<<8192,256>>>(outW, outb, out + OL);
}

// round 6
// speedup vs baseline: 1.3557x; 1.0761x over previous
#include <cuda_runtime.h>
#include <math.h>

#define TT 512
#define BB 128
#define HH 512
#define NZ 2048
#define TB 65536

// ---------------- static device scratch ----------------
__device__ float g_zx[(size_t)TB*NZ];
__device__ float g_hpre[(size_t)TB*HH];
__device__ float g_ys0[(size_t)TB*HH];
__device__ float g_Whp[2][(size_t)NZ*HH];   // swizzled: [(nc*4+k%4)*128 + k/4]
__device__ float g_hbuf[2][BB*HH];          // swizzled: [(row*4+c%4)*128 + c/4]
__device__ unsigned char g_rst[TB];
__device__ unsigned g_cnt[4], g_gen[4];
__device__ int g_rmode;

__device__ __forceinline__ float tf(float x){
  unsigned u; asm("cvt.rna.tf32.f32 %0,%1;" : "=r"(u) : "f"(x));
  return __uint_as_float(u);
}
__device__ __forceinline__ unsigned tfu(float x){
  unsigned u; asm("cvt.rna.tf32.f32 %0,%1;" : "=r"(u) : "f"(x));
  return u;
}
__device__ __forceinline__ void mma8(float* c, const unsigned* a, const unsigned* b){
  asm volatile("mma.sync.aligned.m16n8k8.row.col.f32.tf32.tf32.f32 "
    "{%0,%1,%2,%3},{%4,%5,%6,%7},{%8,%9},{%0,%1,%2,%3};"
    : "+f"(c[0]),"+f"(c[1]),"+f"(c[2]),"+f"(c[3])
    : "r"(a[0]),"r"(a[1]),"r"(a[2]),"r"(a[3]),"r"(b[0]),"r"(b[1]));
}
__device__ __forceinline__ void cpa16(void* dst, const void* src){
  unsigned d = (unsigned)__cvta_generic_to_shared(dst);
  asm volatile("cp.async.cg.shared.global [%0], [%1], 16;" :: "r"(d), "l"(src));
}

// ---------------- resets dtype detect + convert ----------------
__global__ void detect_resets(const unsigned char* p){
  __shared__ int cF, c1;
  if (threadIdx.x == 0){ cF = 0; c1 = 0; }
  __syncthreads();
  for (int i = threadIdx.x; i < 65536; i += 256){
    unsigned char v = p[i];
    if (v == 0x3f || v == 0x80) atomicAdd(&cF, 1);
    else if (v == 1 && (i & 3)) atomicAdd(&c1, 1);
  }
  __syncthreads();
  if (threadIdx.x == 0) g_rmode = cF ? 2 : (c1 ? 1 : 0);
}
__global__ void conv_resets(const void* p){
  int i = blockIdx.x*blockDim.x + threadIdx.x;
  int m = g_rmode;
  bool z;
  if (m == 1)      z = ((const unsigned char*)p)[i] != 0;
  else if (m == 2) z = ((const float*)p)[i] != 0.f;
  else             z = ((const int*)p)[i] != 0;
  g_rst[i] = z ? 1 : 0;
}

// pack Wh[512][2048] -> swizzled tf32-rounded layout
__global__ void pack_wh(const float* __restrict__ Wh, int L){
  for (size_t idx = blockIdx.x*blockDim.x + threadIdx.x; idx < (size_t)HH*NZ;
       idx += (size_t)gridDim.x*blockDim.x){
    int k = idx >> 11, j = idx & (NZ-1);
    int g = j >> 9, r = j & 511;
    int nc = ((r >> 4) << 6) + (g << 4) + (r & 15);
    g_Whp[L][(size_t)(nc*4 + (k & 3))*128 + (k >> 2)] = tf(Wh[idx]);
  }
}

__global__ void init_rec(const float* __restrict__ carryH){
  int i = blockIdx.x*blockDim.x + threadIdx.x;
  if (i < BB*HH){
    int row = i >> 9, col = i & 511;
    g_hbuf[0][(row*4 + (col & 3))*128 + (col >> 2)] = tf(carryH[i]);
  }
  if (i == 0){
    #pragma unroll
    for (int q = 0; q < 4; q++){ g_cnt[q] = 0u; g_gen[q] = 0u; }
  }
}

// ---------------- bulk tf32 GEMM (cp.async double-buffered) ----------------
#define GEMM_SMEM ((2*128*36 + 2*32*136)*4)
#define AS(st,r,k) shA[((st)*128+(r))*36 + (k)]
#define BS(st,k,n) shB[((st)*32+(k))*136 + (n)]

template<bool RELU>
__global__ __launch_bounds__(256) void gemm_tf32(
    const float* __restrict__ Aext, int aSel,
    const float* __restrict__ B, const float* __restrict__ bias,
    int cSel, int N)
{
  extern __shared__ float sh[];
  float* shA = sh;
  float* shB = sh + 2*128*36;
  const float* A = (aSel == 1) ? g_hpre : (aSel == 2) ? g_ys0 : Aext;
  float* C = (cSel == 1) ? g_hpre : g_zx;
  const int mt = blockIdx.y, nt = blockIdx.x, tid = threadIdx.x;
  const int wid = tid >> 5, lane = tid & 31, gID = lane >> 2, tig = lane & 3;
  const int wM = wid >> 1, wN = wid & 1;

  float acc[2][8][4];
  #pragma unroll
  for (int mi = 0; mi < 2; mi++)
    #pragma unroll
    for (int ni = 0; ni < 8; ni++)
      #pragma unroll
      for (int q = 0; q < 4; q++) acc[mi][ni][q] = 0.f;

  auto issue = [&](int kt, int st){
    #pragma unroll
    for (int i = 0; i < 4; i++){
      int idx = tid + i*256, r = idx >> 3, c4 = (idx & 7)*4;
      cpa16(&AS(st, r, c4), &A[(size_t)(mt*128 + r)*512 + kt*32 + c4]);
    }
    #pragma unroll
    for (int i = 0; i < 4; i++){
      int idx = tid + i*256, k = idx >> 5, n4 = (idx & 31)*4;
      cpa16(&BS(st, k, n4), &B[(size_t)(kt*32 + k)*N + nt*128 + n4]);
    }
    asm volatile("cp.async.commit_group;" ::: "memory");
  };

  issue(0, 0);
  issue(1, 1);
  for (int kt = 0; kt < 16; kt++){
    if (kt < 15) asm volatile("cp.async.wait_group 1;" ::: "memory");
    else         asm volatile("cp.async.wait_group 0;" ::: "memory");
    __syncthreads();
    int st = kt & 1;
    #pragma unroll
    for (int kk = 0; kk < 32; kk += 8){
      unsigned a[2][4], b[8][2];
      #pragma unroll
      for (int mi = 0; mi < 2; mi++){
        int r0 = wM*32 + mi*16 + gID;
        a[mi][0] = tfu(AS(st, r0,   kk+tig));
        a[mi][1] = tfu(AS(st, r0+8, kk+tig));
        a[mi][2] = tfu(AS(st, r0,   kk+4+tig));
        a[mi][3] = tfu(AS(st, r0+8, kk+4+tig));
      }
      #pragma unroll
      for (int ni = 0; ni < 8; ni++){
        int n0 = wN*64 + ni*8 + gID;
        b[ni][0] = tfu(BS(st, kk+tig,   n0));
        b[ni][1] = tfu(BS(st, kk+4+tig, n0));
      }
      #pragma unroll
      for (int mi = 0; mi < 2; mi++)
        #pragma unroll
        for (int ni = 0; ni < 8; ni++)
          mma8(acc[mi][ni], a[mi], b[ni]);
    }
    __syncthreads();
    if (kt + 2 < 16) issue(kt + 2, st);
  }

  #pragma unroll
  for (int mi = 0; mi < 2; mi++){
    int r0 = mt*128 + wM*32 + mi*16 + gID;
    #pragma unroll
    for (int ni = 0; ni < 8; ni++){
      int col = nt*128 + wN*64 + ni*8 + tig*2;
      float b0 = bias[col], b1 = bias[col+1];
      float v0 = acc[mi][ni][0]+b0, v1 = acc[mi][ni][1]+b1;
      float v2 = acc[mi][ni][2]+b0, v3 = acc[mi][ni][3]+b1;
      if (RELU){ v0=fmaxf(v0,0.f); v1=fmaxf(v1,0.f); v2=fmaxf(v2,0.f); v3=fmaxf(v3,0.f); }
      *(float2*)&C[(size_t)r0*N + col]     = make_float2(v0, v1);
      *(float2*)&C[(size_t)(r0+8)*N + col] = make_float2(v2, v3);
    }
  }
}

// ---------------- LayerNorm + ReLU ----------------
__global__ __launch_bounds__(256) void ln_relu(
    const float* __restrict__ sc, const float* __restrict__ bi)
{
  int row = blockIdx.x*8 + (threadIdx.x >> 5), lane = threadIdx.x & 31;
  float v[16], s = 0.f, s2 = 0.f;
  #pragma unroll
  for (int j = 0; j < 16; j++){
    v[j] = g_zx[(size_t)row*512 + lane + j*32];
    s += v[j]; s2 += v[j]*v[j];
  }
  #pragma unroll
  for (int o = 16; o; o >>= 1){
    s  += __shfl_xor_sync(0xffffffffu, s,  o);
    s2 += __shfl_xor_sync(0xffffffffu, s2, o);
  }
  float mu = s*(1.f/512.f);
  float var = fmaxf(s2*(1.f/512.f) - mu*mu, 0.f);
  float rs = rsqrtf(var + 1e-6f);
  #pragma unroll
  for (int j = 0; j < 16; j++){
    int col = lane + j*32;
    g_hpre[(size_t)row*512 + col] = fmaxf((v[j]-mu)*rs*sc[col] + bi[col], 0.f);
  }
}

// ---------------- persistent LSTM layer ----------------
// smem: Bs[256][132] + As[128][132] + Zs[2][32][68]
#define RS 132
#define RECSMEM ((256*RS + 128*RS + 2*32*68)*4)
#define ZS1 (32*68)

__device__ __forceinline__ void gbar(int mg){
  __syncthreads();
  if (threadIdx.x == 0){
    __threadfence();
    unsigned g = ((volatile unsigned*)&g_gen[mg])[0];
    if (atomicAdd(&g_cnt[mg], 1u) == 31u){
      g_cnt[mg] = 0u; __threadfence(); atomicAdd(&g_gen[mg], 1u);
    } else {
      while (((volatile unsigned*)&g_gen[mg])[0] == g) { }
      __threadfence();
    }
  }
  __syncthreads();
}

__global__ __launch_bounds__(256,1) void rec_lstm(
    int L, const float* __restrict__ carryC,
    float* __restrict__ ysExt, float* __restrict__ coutP, float* __restrict__ houtP)
{
  extern __shared__ float sm[];
  float* Bs2 = sm;                 // [256][RS]
  float* As2 = sm + 256*RS;        // [128][RS]
  float* Zs  = sm + 384*RS;        // [2][32][68]
  __shared__ int s_rst[32];

  const float* Whp = g_Whp[L];
  float* ys = ysExt ? ysExt : g_ys0;
  const int tid = threadIdx.x, cta = blockIdx.x;
  const int mg = cta >> 5, mbase = mg*32, ni = cta & 31;
  const int wid = tid >> 5, lane = tid & 31, gID = lane >> 2, tig = lane & 3;
  // MMA warps: wid 0..3 -> wN = wid&1 (N 32-half), wK = wid>>1 (K 256-half)
  const int wN = wid & 1, wK = wid >> 1;

  for (int idx = tid; idx < 256*32; idx += 256){
    int r = idx >> 5, j4 = (idx & 31)*4;
    *(float4*)&Bs2[r*RS + j4] =
      *(const float4*)&Whp[(size_t)(ni*256 + r)*128 + j4];
  }
  float cst[2];
  #pragma unroll
  for (int pi = 0; pi < 2; pi++){
    int p = tid + pi*256, r = p >> 4, c = p & 15;
    cst[pi] = carryC[(size_t)(mbase+r)*512 + ni*16 + c];
  }

  const float* pa[4];
  const float* pb[4];
  #pragma unroll
  for (int q = 0; q < 4; q++){
    pa[q] = As2 + ((q*8 + gID)*4 + tig)*RS + wK*64;            // M rows q*8+gID
    pb[q] = Bs2 + ((wN*32 + q*8 + gID)*4 + tig)*RS + wK*64;    // N cols
  }

  for (int t = 0; t < TT; t++){
    const float* hb = g_hbuf[t & 1];
    float* hn = g_hbuf[(t & 1) ^ 1];
    // prefetch Zx into registers
    float pz[2][4];
    #pragma unroll
    for (int pi = 0; pi < 2; pi++){
      int p = tid + pi*256, r = p >> 4, c = p & 15;
      const float* zxr = &g_zx[((size_t)t*128 + mbase + r)*NZ + ni*16 + c];
      pz[pi][0] = __ldg(zxr);
      pz[pi][1] = __ldg(zxr + 512);
      pz[pi][2] = __ldg(zxr + 1024);
      pz[pi][3] = __ldg(zxr + 1536);
    }
    if (tid < 32) s_rst[tid] = g_rst[t*128 + mbase + tid];
    __syncthreads();
    for (int idx = tid; idx < 128*32; idx += 256){
      int r = idx >> 5, j4 = (idx & 31)*4;
      float4 v = __ldcg((const float4*)&hb[(mbase*4 + r)*128 + j4]);
      if (s_rst[r >> 2]){ v.x = 0.f; v.y = 0.f; v.z = 0.f; v.w = 0.f; }
      *(float4*)&As2[r*RS + j4] = v;
    }
    __syncthreads();

    if (wid < 4){
      float acc[2][4][4];
      #pragma unroll
      for (int mt = 0; mt < 2; mt++)
        #pragma unroll
        for (int nb = 0; nb < 4; nb++)
          #pragma unroll
          for (int q = 0; q < 4; q++) acc[mt][nb][q] = 0.f;

      #pragma unroll 2
      for (int j = 0; j < 64; j += 4){
        float4 av[4], bv[4];
        #pragma unroll
        for (int q = 0; q < 4; q++) av[q] = *(const float4*)(pa[q] + j);
        #pragma unroll
        for (int q = 0; q < 4; q++) bv[q] = *(const float4*)(pb[q] + j);
        #pragma unroll
        for (int mt = 0; mt < 2; mt++){
          unsigned Alo[4] = {__float_as_uint(av[2*mt].x), __float_as_uint(av[2*mt+1].x),
                             __float_as_uint(av[2*mt].y), __float_as_uint(av[2*mt+1].y)};
          unsigned Ahi[4] = {__float_as_uint(av[2*mt].z), __float_as_uint(av[2*mt+1].z),
                             __float_as_uint(av[2*mt].w), __float_as_uint(av[2*mt+1].w)};
          #pragma unroll
          for (int nb = 0; nb < 4; nb++){
            unsigned Blo[2] = {__float_as_uint(bv[nb].x), __float_as_uint(bv[nb].y)};
            mma8(acc[mt][nb], Alo, Blo);
            unsigned Bhi[2] = {__float_as_uint(bv[nb].z), __float_as_uint(bv[nb].w)};
            mma8(acc[mt][nb], Ahi, Bhi);
          }
        }
      }
      float* z = Zs + wK*ZS1;
      #pragma unroll
      for (int mt = 0; mt < 2; mt++){
        int zr = mt*16 + gID;
        #pragma unroll
        for (int nb = 0; nb < 4; nb++){
          int zc = wN*32 + nb*8 + tig*2;
          z[zr*68 + zc]         = acc[mt][nb][0];
          z[zr*68 + zc + 1]     = acc[mt][nb][1];
          z[(zr+8)*68 + zc]     = acc[mt][nb][2];
          z[(zr+8)*68 + zc + 1] = acc[mt][nb][3];
        }
      }
    }
    __syncthreads();

    #pragma unroll
    for (int pi = 0; pi < 2; pi++){
      int p = tid + pi*256, r = p >> 4, c = p & 15;
      size_t rg = (size_t)t*128 + mbase + r;
      float zi = Zs[r*68 + c]      + Zs[ZS1 + r*68 + c]      + pz[pi][0];
      float zf = Zs[r*68 + 16 + c] + Zs[ZS1 + r*68 + 16 + c] + pz[pi][1];
      float zg = Zs[r*68 + 32 + c] + Zs[ZS1 + r*68 + 32 + c] + pz[pi][2];
      float zo = Zs[r*68 + 48 + c] + Zs[ZS1 + r*68 + 48 + c] + pz[pi][3];
      float cc = s_rst[r] ? 0.f : cst[pi];
      float ig = 1.f/(1.f + __expf(-zi));
      float fg = 1.f/(1.f + __expf(-zf));
      float og = 1.f/(1.f + __expf(-zo));
      cc = fg*cc + ig*tanhf(zg);
      float nh = og*tanhf(cc);
      cst[pi] = cc;
      int hcol = ni*16 + c;
      __stcg(&hn[((mbase+r)*4 + (c & 3))*128 + ni*4 + (c >> 2)], tf(nh));
      ys[rg*512 + hcol] = nh;
      if (t == TT-1){
        coutP[(size_t)(mbase+r)*512 + hcol] = cc;
        houtP[(size_t)(mbase+r)*512 + hcol] = nh;
      }
    }
    gbar(mg);
  }
}

// ---------------- logits ----------------
__global__ __launch_bounds__(256) void logits_k(
    const float* __restrict__ W, const float* __restrict__ b, float* __restrict__ C)
{
  __shared__ float Ws[512*20];
  int tid = threadIdx.x;
  for (int i = tid; i < 512*20; i += 256) Ws[i] = W[i];
  __syncthreads();
  int row = blockIdx.x*8 + (tid >> 5), lane = tid & 31;
  float acc[20];
  #pragma unroll
  for (int c = 0; c < 20; c++) acc[c] = 0.f;
  #pragma unroll 4
  for (int j = 0; j < 16; j++){
    float a = g_hpre[(size_t)row*512 + lane + j*32];
    const float* w = &Ws[(lane + j*32)*20];
    #pragma unroll
    for (int c = 0; c < 20; c++) acc[c] += a*w[c];
  }
  #pragma unroll
  for (int c = 0; c < 20; c++)
    #pragma unroll
    for (int o = 16; o; o >>= 1) acc[c] += __shfl_xor_sync(0xffffffffu, acc[c], o);
  if (lane < 20) C[(size_t)row*20 + lane] = acc[lane] + b[lane];
}

// ---------------- launcher ----------------
extern "C" void kernel_launch(void* const* d_in, const int*, int, void* d_out_, int){
  const float* x     = (const float*)d_in[0];
  const void*  rsts  = d_in[1];
  const float* cc    = (const float*)d_in[2];
  const float* ch    = (const float*)d_in[3];
  const float* preW  = (const float*)d_in[4];
  const float* preb  = (const float*)d_in[5];
  const float* lns   = (const float*)d_in[6];
  const float* lnb   = (const float*)d_in[7];
  const float* Wi0   = (const float*)d_in[8];
  const float* Wh0   = (const float*)d_in[9];
  const float* b0    = (const float*)d_in[10];
  const float* Wi1   = (const float*)d_in[11];
  const float* Wh1   = (const float*)d_in[12];
  const float* b1    = (const float*)d_in[13];
  const float* postW = (const float*)d_in[14];
  const float* postb = (const float*)d_in[15];
  const float* outW  = (const float*)d_in[16];
  const float* outb  = (const float*)d_in[17];
  float* out = (float*)d_out_;
  const size_t OC = 0, OH = 131072, OL = 262144, OE = 1572864;

  cudaFuncSetAttribute(gemm_tf32<false>, cudaFuncAttributeMaxDynamicSharedMemorySize, GEMM_SMEM);
  cudaFuncSetAttribute(gemm_tf32<true>,  cudaFuncAttributeMaxDynamicSharedMemorySize, GEMM_SMEM);
  cudaFuncSetAttribute(rec_lstm, cudaFuncAttributeMaxDynamicSharedMemorySize, RECSMEM);

  detect_resets<<<1,256>>>((const unsigned char*)rsts);
  conv_resets<<<256,256>>>(rsts);
  dim3 g512(4,512), g2048(16,512);
  gemm_tf32<false><<<g512,256,GEMM_SMEM>>>(x, 0, preW, preb, 0, 512);
  ln_relu<<<8192,256>>>(lns, lnb);
  gemm_tf32<false><<<g2048,256,GEMM_SMEM>>>(nullptr, 1, Wi0, b0, 0, 2048);
  pack_wh<<<2048,512>>>(Wh0, 0);
  init_rec<<<256,256>>>(ch);
  rec_lstm<<<128,256,RECSMEM>>>(0, cc, nullptr, out + OC, out + OH);
  gemm_tf32<false><<<g2048,256,GEMM_SMEM>>>(nullptr, 2, Wi1, b1, 0, 2048);
  pack_wh<<<2048,512>>>(Wh1, 1);
  init_rec<<<256,256>>>(ch + 65536);
  rec_lstm<<<128,256,RECSMEM>>>(1, cc + 65536, out + OE,
                                out + OC + 65536, out + OH + 65536);
  gemm_tf32<true><<<g512,256,GEMM_SMEM>>>(out + OE, 0, postW, postb, 1, 512);
  logits_k<<<8192,256>>>(outW, outb, out + OL);
}

// round 7
// speedup vs baseline: 1.3889x; 1.0245x over previous
#include <cuda_runtime.h>
#include <math.h>

#define TT 512
#define BB 128
#define HH 512
#define NZ 2048
#define TB 65536

// ---------------- static device scratch ----------------
__device__ float g_zx[(size_t)TB*NZ];
__device__ float g_hpre[(size_t)TB*HH];
__device__ float g_ys0[(size_t)TB*HH];
__device__ float g_Whp[2][(size_t)NZ*HH];   // [(nc*4+k%4)*128 + k/4]
__device__ float g_hbuf[2][BB*HH];          // [(row*4+c%4)*128 + c/4]
__device__ float g_wBr[512*2048];           // pre-rounded B (stream-reused)
__device__ unsigned char g_rst[TB];
__device__ unsigned g_cnt[4], g_gen[4];
__device__ int g_rmode;

__device__ __forceinline__ float tf(float x){
  unsigned u; asm("cvt.rna.tf32.f32 %0,%1;" : "=r"(u) : "f"(x));
  return __uint_as_float(u);
}
__device__ __forceinline__ unsigned tfu(float x){
  unsigned u; asm("cvt.rna.tf32.f32 %0,%1;" : "=r"(u) : "f"(x));
  return u;
}
__device__ __forceinline__ void mma8(float* c, const unsigned* a, const unsigned* b){
  asm volatile("mma.sync.aligned.m16n8k8.row.col.f32.tf32.tf32.f32 "
    "{%0,%1,%2,%3},{%4,%5,%6,%7},{%8,%9},{%0,%1,%2,%3};"
    : "+f"(c[0]),"+f"(c[1]),"+f"(c[2]),"+f"(c[3])
    : "r"(a[0]),"r"(a[1]),"r"(a[2]),"r"(a[3]),"r"(b[0]),"r"(b[1]));
}
__device__ __forceinline__ void cpa16(void* dst, const void* src){
  unsigned d = (unsigned)__cvta_generic_to_shared(dst);
  asm volatile("cp.async.cg.shared.global [%0], [%1], 16;" :: "r"(d), "l"(src));
}

// ---------------- resets dtype detect + convert ----------------
__global__ void detect_resets(const unsigned char* p){
  __shared__ int cF, c1;
  if (threadIdx.x == 0){ cF = 0; c1 = 0; }
  __syncthreads();
  for (int i = threadIdx.x; i < 65536; i += 256){
    unsigned char v = p[i];
    if (v == 0x3f || v == 0x80) atomicAdd(&cF, 1);
    else if (v == 1 && (i & 3)) atomicAdd(&c1, 1);
  }
  __syncthreads();
  if (threadIdx.x == 0) g_rmode = cF ? 2 : (c1 ? 1 : 0);
}
__global__ void conv_resets(const void* p){
  int i = blockIdx.x*blockDim.x + threadIdx.x;
  int m = g_rmode;
  bool z;
  if (m == 1)      z = ((const unsigned char*)p)[i] != 0;
  else if (m == 2) z = ((const float*)p)[i] != 0.f;
  else             z = ((const int*)p)[i] != 0;
  g_rst[i] = z ? 1 : 0;
}

// ---------------- weight pre-rounding ----------------
__global__ void pack_b(const float* __restrict__ B, int n){
  for (int i = blockIdx.x*blockDim.x + threadIdx.x; i < n; i += gridDim.x*blockDim.x)
    g_wBr[i] = tf(B[i]);
}

// pack Wh[512][2048] -> swizzled tf32-rounded layout
__global__ void pack_wh(const float* __restrict__ Wh, int L){
  for (size_t idx = blockIdx.x*blockDim.x + threadIdx.x; idx < (size_t)HH*NZ;
       idx += (size_t)gridDim.x*blockDim.x){
    int k = idx >> 11, j = idx & (NZ-1);
    int g = j >> 9, r = j & 511;
    int nc = ((r >> 4) << 6) + (g << 4) + (r & 15);
    g_Whp[L][(size_t)(nc*4 + (k & 3))*128 + (k >> 2)] = tf(Wh[idx]);
  }
}

__global__ void init_rec(const float* __restrict__ carryH){
  int i = blockIdx.x*blockDim.x + threadIdx.x;
  if (i < BB*HH){
    int row = i >> 9, col = i & 511;
    g_hbuf[0][(row*4 + (col & 3))*128 + (col >> 2)] = tf(carryH[i]);
  }
  if (i == 0){
    #pragma unroll
    for (int q = 0; q < 4; q++){ g_cnt[q] = 0u; g_gen[q] = 0u; }
  }
}

// ---------------- bulk tf32 GEMM (cp.async double-buffered, 2 CTA/SM) ------
#define GEMM_SMEM ((2*128*36 + 2*32*136)*4)
#define AS(st,r,k) shA[((st)*128+(r))*36 + (k)]
#define BS(st,k,n) shB[((st)*32+(k))*136 + (n)]

template<bool RELU, bool CVTA>
__global__ __launch_bounds__(256,2) void gemm_tf32(
    const float* __restrict__ Aext, int aSel,
    const float* __restrict__ bias, int cSel, int N)
{
  extern __shared__ float sh[];
  float* shA = sh;
  float* shB = sh + 2*128*36;
  const float* A = (aSel == 1) ? g_hpre : (aSel == 2) ? g_ys0 : Aext;
  const float* B = g_wBr;
  float* C = (cSel == 1) ? g_hpre : g_zx;
  const int mt = blockIdx.y, nt = blockIdx.x, tid = threadIdx.x;
  const int wid = tid >> 5, lane = tid & 31, gID = lane >> 2, tig = lane & 3;
  const int wM = wid >> 1, wN = wid & 1;

  float acc[2][8][4];
  #pragma unroll
  for (int mi = 0; mi < 2; mi++)
    #pragma unroll
    for (int ni = 0; ni < 8; ni++)
      #pragma unroll
      for (int q = 0; q < 4; q++) acc[mi][ni][q] = 0.f;

  auto issue = [&](int kt, int st){
    #pragma unroll
    for (int i = 0; i < 4; i++){
      int idx = tid + i*256, r = idx >> 3, c4 = (idx & 7)*4;
      cpa16(&AS(st, r, c4), &A[(size_t)(mt*128 + r)*512 + kt*32 + c4]);
    }
    #pragma unroll
    for (int i = 0; i < 4; i++){
      int idx = tid + i*256, k = idx >> 5, n4 = (idx & 31)*4;
      cpa16(&BS(st, k, n4), &B[(size_t)(kt*32 + k)*N + nt*128 + n4]);
    }
    asm volatile("cp.async.commit_group;" ::: "memory");
  };

  issue(0, 0);
  issue(1, 1);
  for (int kt = 0; kt < 16; kt++){
    if (kt < 15) asm volatile("cp.async.wait_group 1;" ::: "memory");
    else         asm volatile("cp.async.wait_group 0;" ::: "memory");
    __syncthreads();
    int st = kt & 1;
    #pragma unroll
    for (int kk = 0; kk < 32; kk += 8){
      unsigned a[2][4], b[8][2];
      #pragma unroll
      for (int mi = 0; mi < 2; mi++){
        int r0 = wM*32 + mi*16 + gID;
        if (CVTA){
          a[mi][0] = tfu(AS(st, r0,   kk+tig));
          a[mi][1] = tfu(AS(st, r0+8, kk+tig));
          a[mi][2] = tfu(AS(st, r0,   kk+4+tig));
          a[mi][3] = tfu(AS(st, r0+8, kk+4+tig));
        } else {
          a[mi][0] = __float_as_uint(AS(st, r0,   kk+tig));
          a[mi][1] = __float_as_uint(AS(st, r0+8, kk+tig));
          a[mi][2] = __float_as_uint(AS(st, r0,   kk+4+tig));
          a[mi][3] = __float_as_uint(AS(st, r0+8, kk+4+tig));
        }
      }
      #pragma unroll
      for (int ni = 0; ni < 8; ni++){
        int n0 = wN*64 + ni*8 + gID;
        b[ni][0] = __float_as_uint(BS(st, kk+tig,   n0));
        b[ni][1] = __float_as_uint(BS(st, kk+4+tig, n0));
      }
      #pragma unroll
      for (int mi = 0; mi < 2; mi++)
        #pragma unroll
        for (int ni = 0; ni < 8; ni++)
          mma8(acc[mi][ni], a[mi], b[ni]);
    }
    __syncthreads();
    if (kt + 2 < 16) issue(kt + 2, st);
  }

  #pragma unroll
  for (int mi = 0; mi < 2; mi++){
    int r0 = mt*128 + wM*32 + mi*16 + gID;
    #pragma unroll
    for (int ni = 0; ni < 8; ni++){
      int col = nt*128 + wN*64 + ni*8 + tig*2;
      float b0 = bias[col], b1 = bias[col+1];
      float v0 = acc[mi][ni][0]+b0, v1 = acc[mi][ni][1]+b1;
      float v2 = acc[mi][ni][2]+b0, v3 = acc[mi][ni][3]+b1;
      if (RELU){ v0=fmaxf(v0,0.f); v1=fmaxf(v1,0.f); v2=fmaxf(v2,0.f); v3=fmaxf(v3,0.f); }
      *(float2*)&C[(size_t)r0*N + col]     = make_float2(v0, v1);
      *(float2*)&C[(size_t)(r0+8)*N + col] = make_float2(v2, v3);
    }
  }
}

// ---------------- LayerNorm + ReLU (stores tf32-rounded) ----------------
__global__ __launch_bounds__(256) void ln_relu(
    const float* __restrict__ sc, const float* __restrict__ bi)
{
  int row = blockIdx.x*8 + (threadIdx.x >> 5), lane = threadIdx.x & 31;
  float v[16], s = 0.f, s2 = 0.f;
  #pragma unroll
  for (int j = 0; j < 16; j++){
    v[j] = g_zx[(size_t)row*512 + lane + j*32];
    s += v[j]; s2 += v[j]*v[j];
  }
  #pragma unroll
  for (int o = 16; o; o >>= 1){
    s  += __shfl_xor_sync(0xffffffffu, s,  o);
    s2 += __shfl_xor_sync(0xffffffffu, s2, o);
  }
  float mu = s*(1.f/512.f);
  float var = fmaxf(s2*(1.f/512.f) - mu*mu, 0.f);
  float rs = rsqrtf(var + 1e-6f);
  #pragma unroll
  for (int j = 0; j < 16; j++){
    int col = lane + j*32;
    g_hpre[(size_t)row*512 + col] = tf(fmaxf((v[j]-mu)*rs*sc[col] + bi[col], 0.f));
  }
}

// ---------------- persistent LSTM layer ----------------
// smem (floats): Bs 256x128 swizzled | As 128x128 swizzled | Zs 4x32x64
#define RECSMEM ((256*128 + 128*128 + 4*32*64)*4)
#define SWZ(r,j) ((j) ^ (((r) & 7) << 2))

__device__ __forceinline__ void gbar(int mg){
  __syncthreads();
  if (threadIdx.x == 0){
    __threadfence();
    unsigned g = ((volatile unsigned*)&g_gen[mg])[0];
    if (atomicAdd(&g_cnt[mg], 1u) == 31u){
      g_cnt[mg] = 0u; __threadfence(); atomicAdd(&g_gen[mg], 1u);
    } else {
      while (((volatile unsigned*)&g_gen[mg])[0] == g) { }
      __threadfence();
    }
  }
  __syncthreads();
}

__global__ __launch_bounds__(256,1) void rec_lstm(
    int L, const float* __restrict__ carryC,
    float* __restrict__ ysExt, float* __restrict__ coutP, float* __restrict__ houtP)
{
  extern __shared__ float sm[];
  float* Bs2 = sm;                 // [256][128] swizzled
  float* As2 = sm + 256*128;       // [128][128] swizzled
  float* Zs  = sm + 384*128;       // [4][32][64]
  __shared__ int s_rst[32];

  const float* Whp = g_Whp[L];
  float* ys = ysExt ? ysExt : g_ys0;
  const int tid = threadIdx.x, cta = blockIdx.x;
  const int mg = cta >> 5, mbase = mg*32, ni = cta & 31;
  const int wid = tid >> 5, lane = tid & 31, gID = lane >> 2, tig = lane & 3;
  // 8 MMA warps: wN = N 32-half, wK = K 128-quarter
  const int wN = wid & 1, wK = wid >> 1;

  for (int idx = tid; idx < 256*32; idx += 256){
    int r = idx >> 5, j4 = (idx & 31)*4;
    *(float4*)&Bs2[r*128 + SWZ(r, j4)] =
      *(const float4*)&Whp[(size_t)(ni*256 + r)*128 + j4];
  }
  float cst[2];
  #pragma unroll
  for (int pi = 0; pi < 2; pi++){
    int p = tid + pi*256, r = p >> 4, c = p & 15;
    cst[pi] = carryC[(size_t)(mbase+r)*512 + ni*16 + c];
  }

  int baseA[4], sA[4], baseB[4], sB[4];
  #pragma unroll
  for (int q = 0; q < 4; q++){
    int ra = (q*8 + gID)*4 + tig;
    int rb = (wN*32 + q*8 + gID)*4 + tig;
    baseA[q] = ra*128; sA[q] = (ra & 7) << 2;
    baseB[q] = rb*128; sB[q] = (rb & 7) << 2;
  }

  for (int t = 0; t < TT; t++){
    const float* hb = g_hbuf[t & 1];
    float* hn = g_hbuf[(t & 1) ^ 1];
    // prefetch Zx into registers
    float pz[2][4];
    #pragma unroll
    for (int pi = 0; pi < 2; pi++){
      int p = tid + pi*256, r = p >> 4, c = p & 15;
      const float* zxr = &g_zx[((size_t)t*128 + mbase + r)*NZ + ni*16 + c];
      pz[pi][0] = __ldg(zxr);
      pz[pi][1] = __ldg(zxr + 512);
      pz[pi][2] = __ldg(zxr + 1024);
      pz[pi][3] = __ldg(zxr + 1536);
    }
    if (tid < 32) s_rst[tid] = g_rst[t*128 + mbase + tid];
    __syncthreads();
    for (int idx = tid; idx < 128*32; idx += 256){
      int r = idx >> 5, j4 = (idx & 31)*4;
      float4 v = __ldcg((const float4*)&hb[(mbase*4 + r)*128 + j4]);
      if (s_rst[r >> 2]){ v.x = 0.f; v.y = 0.f; v.z = 0.f; v.w = 0.f; }
      *(float4*)&As2[r*128 + SWZ(r, j4)] = v;
    }
    __syncthreads();

    {
      float acc[2][4][4];
      #pragma unroll
      for (int mt2 = 0; mt2 < 2; mt2++)
        #pragma unroll
        for (int nb = 0; nb < 4; nb++)
          #pragma unroll
          for (int q = 0; q < 4; q++) acc[mt2][nb][q] = 0.f;

      #pragma unroll
      for (int jj = 0; jj < 32; jj += 4){
        int j = wK*32 + jj;
        float4 av[4], bv[4];
        #pragma unroll
        for (int q = 0; q < 4; q++)
          av[q] = *(const float4*)&As2[baseA[q] + (j ^ sA[q])];
        #pragma unroll
        for (int q = 0; q < 4; q++)
          bv[q] = *(const float4*)&Bs2[baseB[q] + (j ^ sB[q])];
        #pragma unroll
        for (int mt2 = 0; mt2 < 2; mt2++){
          unsigned Alo[4] = {__float_as_uint(av[2*mt2].x), __float_as_uint(av[2*mt2+1].x),
                             __float_as_uint(av[2*mt2].y), __float_as_uint(av[2*mt2+1].y)};
          unsigned Ahi[4] = {__float_as_uint(av[2*mt2].z), __float_as_uint(av[2*mt2+1].z),
                             __float_as_uint(av[2*mt2].w), __float_as_uint(av[2*mt2+1].w)};
          #pragma unroll
          for (int nb = 0; nb < 4; nb++){
            unsigned Blo[2] = {__float_as_uint(bv[nb].x), __float_as_uint(bv[nb].y)};
            mma8(acc[mt2][nb], Alo, Blo);
            unsigned Bhi[2] = {__float_as_uint(bv[nb].z), __float_as_uint(bv[nb].w)};
            mma8(acc[mt2][nb], Ahi, Bhi);
          }
        }
      }
      float* z = Zs + wK*(32*64);
      #pragma unroll
      for (int mt2 = 0; mt2 < 2; mt2++){
        int zr = mt2*16 + gID;
        #pragma unroll
        for (int nb = 0; nb < 4; nb++){
          int zc = wN*32 + nb*8 + tig*2;
          z[zr*64 + zc]         = acc[mt2][nb][0];
          z[zr*64 + zc + 1]     = acc[mt2][nb][1];
          z[(zr+8)*64 + zc]     = acc[mt2][nb][2];
          z[(zr+8)*64 + zc + 1] = acc[mt2][nb][3];
        }
      }
    }
    __syncthreads();

    #pragma unroll
    for (int pi = 0; pi < 2; pi++){
      int p = tid + pi*256, r = p >> 4, c = p & 15;
      size_t rg = (size_t)t*128 + mbase + r;
      float zi = pz[pi][0], zf = pz[pi][1], zg = pz[pi][2], zo = pz[pi][3];
      #pragma unroll
      for (int k4 = 0; k4 < 4; k4++){
        const float* z = Zs + k4*(32*64) + r*64;
        zi += z[c]; zf += z[16 + c]; zg += z[32 + c]; zo += z[48 + c];
      }
      float cc = s_rst[r] ? 0.f : cst[pi];
      float ig = 1.f/(1.f + __expf(-zi));
      float fg = 1.f/(1.f + __expf(-zf));
      float og = 1.f/(1.f + __expf(-zo));
      cc = fg*cc + ig*tanhf(zg);
      float nh = og*tanhf(cc);
      float nhr = tf(nh);
      cst[pi] = cc;
      int hcol = ni*16 + c;
      __stcg(&hn[((mbase+r)*4 + (c & 3))*128 + ni*4 + (c >> 2)], nhr);
      ys[rg*512 + hcol] = (L == 0) ? nhr : nh;
      if (t == TT-1){
        coutP[(size_t)(mbase+r)*512 + hcol] = cc;
        houtP[(size_t)(mbase+r)*512 + hcol] = nh;
      }
    }
    gbar(mg);
  }
}

// ---------------- logits ----------------
__global__ __launch_bounds__(256) void logits_k(
    const float* __restrict__ W, const float* __restrict__ b, float* __restrict__ C)
{
  __shared__ float Ws[512*20];
  int tid = threadIdx.x;
  for (int i = tid; i < 512*20; i += 256) Ws[i] = W[i];
  __syncthreads();
  int row = blockIdx.x*8 + (tid >> 5), lane = tid & 31;
  float acc[20];
  #pragma unroll
  for (int c = 0; c < 20; c++) acc[c] = 0.f;
  #pragma unroll 4
  for (int j = 0; j < 16; j++){
    float a = g_hpre[(size_t)row*512 + lane + j*32];
    const float* w = &Ws[(lane + j*32)*20];
    #pragma unroll
    for (int c = 0; c < 20; c++) acc[c] += a*w[c];
  }
  #pragma unroll
  for (int c = 0; c < 20; c++)
    #pragma unroll
    for (int o = 16; o; o >>= 1) acc[c] += __shfl_xor_sync(0xffffffffu, acc[c], o);
  if (lane < 20) C[(size_t)row*20 + lane] = acc[lane] + b[lane];
}

// ---------------- launcher ----------------
extern "C" void kernel_launch(void* const* d_in, const int*, int, void* d_out_, int){
  const float* x     = (const float*)d_in[0];
  const void*  rsts  = d_in[1];
  const float* cc    = (const float*)d_in[2];
  const float* ch    = (const float*)d_in[3];
  const float* preW  = (const float*)d_in[4];
  const float* preb  = (const float*)d_in[5];
  const float* lns   = (const float*)d_in[6];
  const float* lnb   = (const float*)d_in[7];
  const float* Wi0   = (const float*)d_in[8];
  const float* Wh0   = (const float*)d_in[9];
  const float* b0    = (const float*)d_in[10];
  const float* Wi1   = (const float*)d_in[11];
  const float* Wh1   = (const float*)d_in[12];
  const float* b1    = (const float*)d_in[13];
  const float* postW = (const float*)d_in[14];
  const float* postb = (const float*)d_in[15];
  const float* outW  = (const float*)d_in[16];
  const float* outb  = (const float*)d_in[17];
  float* out = (float*)d_out_;
  const size_t OC = 0, OH = 131072, OL = 262144, OE = 1572864;

  cudaFuncSetAttribute(gemm_tf32<false,true>,  cudaFuncAttributeMaxDynamicSharedMemorySize, GEMM_SMEM);
  cudaFuncSetAttribute(gemm_tf32<false,false>, cudaFuncAttributeMaxDynamicSharedMemorySize, GEMM_SMEM);
  cudaFuncSetAttribute(gemm_tf32<true,true>,   cudaFuncAttributeMaxDynamicSharedMemorySize, GEMM_SMEM);
  cudaFuncSetAttribute(rec_lstm, cudaFuncAttributeMaxDynamicSharedMemorySize, RECSMEM);

  detect_resets<<<1,256>>>((const unsigned char*)rsts);
  conv_resets<<<256,256>>>(rsts);
  dim3 g512(4,512), g2048(16,512);

  pack_b<<<512,256>>>(preW, 512*512);
  gemm_tf32<false,true><<<g512,256,GEMM_SMEM>>>(x, 0, preb, 0, 512);
  ln_relu<<<8192,256>>>(lns, lnb);

  pack_b<<<2048,256>>>(Wi0, 512*2048);
  gemm_tf32<false,false><<<g2048,256,GEMM_SMEM>>>(nullptr, 1, b0, 0, 2048);
  pack_wh<<<2048,512>>>(Wh0, 0);
  init_rec<<<256,256>>>(ch);
  rec_lstm<<<128,256,RECSMEM>>>(0, cc, nullptr, out + OC, out + OH);

  pack_b<<<2048,256>>>(Wi1, 512*2048);
  gemm_tf32<false,false><<<g2048,256,GEMM_SMEM>>>(nullptr, 2, b1, 0, 2048);
  pack_wh<<<2048,512>>>(Wh1, 1);
  init_rec<<<256,256>>>(ch + 65536);
  rec_lstm<<<128,256,RECSMEM>>>(1, cc + 65536, out + OE,
                                out + OC + 65536, out + OH + 65536);

  pack_b<<<512,256>>>(postW, 512*512);
  gemm_tf32<true,true><<<g512,256,GEMM_SMEM>>>(out + OE, 0, postb, 1, 512);
  logits_k<<<8192,256>>>(outW, outb, out + OL);
}

// round 8
// speedup vs baseline: 1.6649x; 1.1988x over previous
#include <cuda_runtime.h>
#include <math.h>

#define TT 512
#define BB 128
#define HH 512
#define NZ 2048
#define TB 65536

// ---------------- static device scratch ----------------
__device__ float g_zx[(size_t)TB*NZ];
__device__ float g_hpre[(size_t)TB*HH];
__device__ float g_ys0[(size_t)TB*HH];
__device__ float g_Whp[2][(size_t)NZ*HH];   // [(nc*4+k%4)*128 + k/4]
__device__ float g_hbuf[2][BB*HH];          // [(row*4+c%4)*128 + c/4]
__device__ float g_wBr[512*2048];           // pre-rounded B (stream-reused)
__device__ unsigned char g_rst[TB];
__device__ unsigned g_cnt[4], g_gen[4];
__device__ int g_rmode;

__device__ __forceinline__ float tf(float x){
  unsigned u; asm("cvt.rna.tf32.f32 %0,%1;" : "=r"(u) : "f"(x));
  return __uint_as_float(u);
}
__device__ __forceinline__ unsigned tfu(float x){
  unsigned u; asm("cvt.rna.tf32.f32 %0,%1;" : "=r"(u) : "f"(x));
  return u;
}
__device__ __forceinline__ void mma8(float* c, const unsigned* a, const unsigned* b){
  asm volatile("mma.sync.aligned.m16n8k8.row.col.f32.tf32.tf32.f32 "
    "{%0,%1,%2,%3},{%4,%5,%6,%7},{%8,%9},{%0,%1,%2,%3};"
    : "+f"(c[0]),"+f"(c[1]),"+f"(c[2]),"+f"(c[3])
    : "r"(a[0]),"r"(a[1]),"r"(a[2]),"r"(a[3]),"r"(b[0]),"r"(b[1]));
}
__device__ __forceinline__ void cpa16(void* dst, const void* src){
  unsigned d = (unsigned)__cvta_generic_to_shared(dst);
  asm volatile("cp.async.cg.shared.global [%0], [%1], 16;" :: "r"(d), "l"(src));
}

// ---------------- resets dtype detect + convert ----------------
__global__ void detect_resets(const unsigned char* p){
  __shared__ int cF, c1;
  if (threadIdx.x == 0){ cF = 0; c1 = 0; }
  __syncthreads();
  for (int i = threadIdx.x; i < 65536; i += 256){
    unsigned char v = p[i];
    if (v == 0x3f || v == 0x80) atomicAdd(&cF, 1);
    else if (v == 1 && (i & 3)) atomicAdd(&c1, 1);
  }
  __syncthreads();
  if (threadIdx.x == 0) g_rmode = cF ? 2 : (c1 ? 1 : 0);
}
__global__ void conv_resets(const void* p){
  int i = blockIdx.x*blockDim.x + threadIdx.x;
  int m = g_rmode;
  bool z;
  if (m == 1)      z = ((const unsigned char*)p)[i] != 0;
  else if (m == 2) z = ((const float*)p)[i] != 0.f;
  else             z = ((const int*)p)[i] != 0;
  g_rst[i] = z ? 1 : 0;
}

// ---------------- weight pre-rounding ----------------
__global__ void pack_b(const float* __restrict__ B, int n){
  for (int i = blockIdx.x*blockDim.x + threadIdx.x; i < n; i += gridDim.x*blockDim.x)
    g_wBr[i] = tf(B[i]);
}

// pack Wh[512][2048] -> swizzled tf32-rounded layout
__global__ void pack_wh(const float* __restrict__ Wh, int L){
  for (size_t idx = blockIdx.x*blockDim.x + threadIdx.x; idx < (size_t)HH*NZ;
       idx += (size_t)gridDim.x*blockDim.x){
    int k = idx >> 11, j = idx & (NZ-1);
    int g = j >> 9, r = j & 511;
    int nc = ((r >> 4) << 6) + (g << 4) + (r & 15);
    g_Whp[L][(size_t)(nc*4 + (k & 3))*128 + (k >> 2)] = tf(Wh[idx]);
  }
}

// init h buffer with reset for t=0 pre-applied
__global__ void init_rec(const float* __restrict__ carryH){
  int i = blockIdx.x*blockDim.x + threadIdx.x;
  if (i < BB*HH){
    int row = i >> 9, col = i & 511;
    float v = g_rst[row] ? 0.f : tf(carryH[i]);
    g_hbuf[0][(row*4 + (col & 3))*128 + (col >> 2)] = v;
  }
  if (i == 0){
    #pragma unroll
    for (int q = 0; q < 4; q++){ g_cnt[q] = 0u; g_gen[q] = 0u; }
  }
}

// ---------------- bulk tf32 GEMM (3-stage cp.async pipeline) ----------------
#define GEMM_SMEM (3*(128*36 + 32*136)*4)
#define AS(st,r,k) shA[((st)*128+(r))*36 + (k)]
#define BS(st,k,n) shB[((st)*32+(k))*136 + (n)]

template<bool RELU, bool CVTA>
__global__ __launch_bounds__(256) void gemm_tf32(
    const float* __restrict__ Aext, int aSel,
    const float* __restrict__ bias, int cSel, int N)
{
  extern __shared__ float sh[];
  float* shA = sh;
  float* shB = sh + 3*128*36;
  const float* A = (aSel == 1) ? g_hpre : (aSel == 2) ? g_ys0 : Aext;
  const float* B = g_wBr;
  float* C = (cSel == 1) ? g_hpre : g_zx;
  const int mt = blockIdx.y, nt = blockIdx.x, tid = threadIdx.x;
  const int wid = tid >> 5, lane = tid & 31, gID = lane >> 2, tig = lane & 3;
  const int wM = wid >> 1, wN = wid & 1;

  float acc[2][8][4];
  #pragma unroll
  for (int mi = 0; mi < 2; mi++)
    #pragma unroll
    for (int ni = 0; ni < 8; ni++)
      #pragma unroll
      for (int q = 0; q < 4; q++) acc[mi][ni][q] = 0.f;

  auto issue = [&](int kt, int st){
    #pragma unroll
    for (int i = 0; i < 4; i++){
      int idx = tid + i*256, r = idx >> 3, c4 = (idx & 7)*4;
      cpa16(&AS(st, r, c4), &A[(size_t)(mt*128 + r)*512 + kt*32 + c4]);
    }
    #pragma unroll
    for (int i = 0; i < 4; i++){
      int idx = tid + i*256, k = idx >> 5, n4 = (idx & 31)*4;
      cpa16(&BS(st, k, n4), &B[(size_t)(kt*32 + k)*N + nt*128 + n4]);
    }
    asm volatile("cp.async.commit_group;" ::: "memory");
  };

  issue(0, 0); issue(1, 1); issue(2, 2);
  int st = 0;
  for (int kt = 0; kt < 16; kt++){
    if (kt <= 13)      asm volatile("cp.async.wait_group 2;" ::: "memory");
    else if (kt == 14) asm volatile("cp.async.wait_group 1;" ::: "memory");
    else               asm volatile("cp.async.wait_group 0;" ::: "memory");
    __syncthreads();
    #pragma unroll
    for (int kk = 0; kk < 32; kk += 8){
      unsigned a[2][4], b[8][2];
      #pragma unroll
      for (int mi = 0; mi < 2; mi++){
        int r0 = wM*32 + mi*16 + gID;
        if (CVTA){
          a[mi][0] = tfu(AS(st, r0,   kk+tig));
          a[mi][1] = tfu(AS(st, r0+8, kk+tig));
          a[mi][2] = tfu(AS(st, r0,   kk+4+tig));
          a[mi][3] = tfu(AS(st, r0+8, kk+4+tig));
        } else {
          a[mi][0] = __float_as_uint(AS(st, r0,   kk+tig));
          a[mi][1] = __float_as_uint(AS(st, r0+8, kk+tig));
          a[mi][2] = __float_as_uint(AS(st, r0,   kk+4+tig));
          a[mi][3] = __float_as_uint(AS(st, r0+8, kk+4+tig));
        }
      }
      #pragma unroll
      for (int ni = 0; ni < 8; ni++){
        int n0 = wN*64 + ni*8 + gID;
        b[ni][0] = __float_as_uint(BS(st, kk+tig,   n0));
        b[ni][1] = __float_as_uint(BS(st, kk+4+tig, n0));
      }
      #pragma unroll
      for (int mi = 0; mi < 2; mi++)
        #pragma unroll
        for (int ni = 0; ni < 8; ni++)
          mma8(acc[mi][ni], a[mi], b[ni]);
    }
    __syncthreads();
    if (kt + 3 < 16) issue(kt + 3, st);
    st = (st == 2) ? 0 : st + 1;
  }

  #pragma unroll
  for (int mi = 0; mi < 2; mi++){
    int r0 = mt*128 + wM*32 + mi*16 + gID;
    #pragma unroll
    for (int ni = 0; ni < 8; ni++){
      int col = nt*128 + wN*64 + ni*8 + tig*2;
      float b0 = bias[col], b1 = bias[col+1];
      float v0 = acc[mi][ni][0]+b0, v1 = acc[mi][ni][1]+b1;
      float v2 = acc[mi][ni][2]+b0, v3 = acc[mi][ni][3]+b1;
      if (RELU){ v0=fmaxf(v0,0.f); v1=fmaxf(v1,0.f); v2=fmaxf(v2,0.f); v3=fmaxf(v3,0.f); }
      *(float2*)&C[(size_t)r0*N + col]     = make_float2(v0, v1);
      *(float2*)&C[(size_t)(r0+8)*N + col] = make_float2(v2, v3);
    }
  }
}

// ---------------- LayerNorm + ReLU (stores tf32-rounded) ----------------
__global__ __launch_bounds__(256) void ln_relu(
    const float* __restrict__ sc, const float* __restrict__ bi)
{
  int row = blockIdx.x*8 + (threadIdx.x >> 5), lane = threadIdx.x & 31;
  float v[16], s = 0.f, s2 = 0.f;
  #pragma unroll
  for (int j = 0; j < 16; j++){
    v[j] = g_zx[(size_t)row*512 + lane + j*32];
    s += v[j]; s2 += v[j]*v[j];
  }
  #pragma unroll
  for (int o = 16; o; o >>= 1){
    s  += __shfl_xor_sync(0xffffffffu, s,  o);
    s2 += __shfl_xor_sync(0xffffffffu, s2, o);
  }
  float mu = s*(1.f/512.f);
  float var = fmaxf(s2*(1.f/512.f) - mu*mu, 0.f);
  float rs = rsqrtf(var + 1e-6f);
  #pragma unroll
  for (int j = 0; j < 16; j++){
    int col = lane + j*32;
    g_hpre[(size_t)row*512 + col] = tf(fmaxf((v[j]-mu)*rs*sc[col] + bi[col], 0.f));
  }
}

// ---------------- persistent LSTM layer ----------------
// smem (floats): Bs 256x128 swizzled | As 128x128 swizzled | Zs 4x32x64
#define RECSMEM ((256*128 + 128*128 + 4*32*64)*4)
#define SWZ(r,j) ((j) ^ (((r) & 7) << 2))

__device__ __forceinline__ void gbar(int mg){
  __syncthreads();
  if (threadIdx.x == 0){
    unsigned g0;
    asm volatile("ld.relaxed.gpu.global.u32 %0, [%1];"
                 : "=r"(g0) : "l"(&g_gen[mg]) : "memory");
    unsigned old;
    asm volatile("atom.add.release.gpu.global.u32 %0, [%1], %2;"
                 : "=r"(old) : "l"(&g_cnt[mg]), "r"(1u) : "memory");
    if (old == 31u){
      asm volatile("st.relaxed.gpu.global.u32 [%0], %1;"
                   :: "l"(&g_cnt[mg]), "r"(0u) : "memory");
      __threadfence();
      asm volatile("red.release.gpu.global.add.u32 [%0], %1;"
                   :: "l"(&g_gen[mg]), "r"(1u) : "memory");
    } else {
      unsigned g;
      do {
        asm volatile("ld.acquire.gpu.global.u32 %0, [%1];"
                     : "=r"(g) : "l"(&g_gen[mg]) : "memory");
      } while (g == g0);
    }
  }
  __syncthreads();
}

__global__ __launch_bounds__(256,1) void rec_lstm(
    int L, const float* __restrict__ carryC,
    float* __restrict__ ysExt, float* __restrict__ coutP, float* __restrict__ houtP)
{
  extern __shared__ float sm[];
  float* Bs2 = sm;                 // [256][128] swizzled
  float* As2 = sm + 256*128;       // [128][128] swizzled
  float* Zs  = sm + 384*128;       // [4][32][64]

  const float* Whp = g_Whp[L];
  float* ys = ysExt ? ysExt : g_ys0;
  const int tid = threadIdx.x, cta = blockIdx.x;
  const int mg = cta >> 5, mbase = mg*32, ni = cta & 31;
  const int wid = tid >> 5, lane = tid & 31, gID = lane >> 2, tig = lane & 3;
  const int wN = wid & 1, wK = wid >> 1;

  for (int idx = tid; idx < 256*32; idx += 256){
    int r = idx >> 5, j4 = (idx & 31)*4;
    *(float4*)&Bs2[r*128 + SWZ(r, j4)] =
      *(const float4*)&Whp[(size_t)(ni*256 + r)*128 + j4];
  }
  float cst[2];
  #pragma unroll
  for (int pi = 0; pi < 2; pi++){
    int p = tid + pi*256, r = p >> 4, c = p & 15;
    cst[pi] = carryC[(size_t)(mbase+r)*512 + ni*16 + c];
  }

  int baseA[4], sA[4], baseB[4], sB[4];
  #pragma unroll
  for (int q = 0; q < 4; q++){
    int ra = (q*8 + gID)*4 + tig;
    int rb = (wN*32 + q*8 + gID)*4 + tig;
    baseA[q] = ra*128; sA[q] = (ra & 7) << 2;
    baseB[q] = rb*128; sB[q] = (rb & 7) << 2;
  }

  for (int t = 0; t < TT; t++){
    const float* hb = g_hbuf[t & 1];
    float* hn = g_hbuf[(t & 1) ^ 1];

    // As fill: pure cp.async (h already reset-masked by producer)
    #pragma unroll
    for (int i = 0; i < 16; i++){
      int idx = tid + i*256;
      int r = idx >> 5, j4 = (idx & 31)*4;
      cpa16(&As2[r*128 + SWZ(r, j4)], &hb[(mbase*4 + r)*128 + j4]);
    }
    asm volatile("cp.async.commit_group;" ::: "memory");

    // prefetch Zx + resets into registers (overlaps cp.async)
    float pz[2][4]; int rc[2], rn[2];
    #pragma unroll
    for (int pi = 0; pi < 2; pi++){
      int p = tid + pi*256, r = p >> 4, c = p & 15;
      const float* zxr = &g_zx[((size_t)t*128 + mbase + r)*NZ + ni*16 + c];
      pz[pi][0] = __ldg(zxr);
      pz[pi][1] = __ldg(zxr + 512);
      pz[pi][2] = __ldg(zxr + 1024);
      pz[pi][3] = __ldg(zxr + 1536);
      rc[pi] = g_rst[t*128 + mbase + r];
      rn[pi] = (t == TT-1) ? 0 : g_rst[(t+1)*128 + mbase + r];
    }
    asm volatile("cp.async.wait_group 0;" ::: "memory");
    __syncthreads();

    {
      float acc[2][4][4];
      #pragma unroll
      for (int mt2 = 0; mt2 < 2; mt2++)
        #pragma unroll
        for (int nb = 0; nb < 4; nb++)
          #pragma unroll
          for (int q = 0; q < 4; q++) acc[mt2][nb][q] = 0.f;

      #pragma unroll
      for (int jj = 0; jj < 32; jj += 4){
        int j = wK*32 + jj;
        float4 av[4], bv[4];
        #pragma unroll
        for (int q = 0; q < 4; q++)
          av[q] = *(const float4*)&As2[baseA[q] + (j ^ sA[q])];
        #pragma unroll
        for (int q = 0; q < 4; q++)
          bv[q] = *(const float4*)&Bs2[baseB[q] + (j ^ sB[q])];
        #pragma unroll
        for (int mt2 = 0; mt2 < 2; mt2++){
          unsigned Alo[4] = {__float_as_uint(av[2*mt2].x), __float_as_uint(av[2*mt2+1].x),
                             __float_as_uint(av[2*mt2].y), __float_as_uint(av[2*mt2+1].y)};
          unsigned Ahi[4] = {__float_as_uint(av[2*mt2].z), __float_as_uint(av[2*mt2+1].z),
                             __float_as_uint(av[2*mt2].w), __float_as_uint(av[2*mt2+1].w)};
          #pragma unroll
          for (int nb = 0; nb < 4; nb++){
            unsigned Blo[2] = {__float_as_uint(bv[nb].x), __float_as_uint(bv[nb].y)};
            mma8(acc[mt2][nb], Alo, Blo);
            unsigned Bhi[2] = {__float_as_uint(bv[nb].z), __float_as_uint(bv[nb].w)};
            mma8(acc[mt2][nb], Ahi, Bhi);
          }
        }
      }
      float* z = Zs + wK*(32*64);
      #pragma unroll
      for (int mt2 = 0; mt2 < 2; mt2++){
        int zr = mt2*16 + gID;
        #pragma unroll
        for (int nb = 0; nb < 4; nb++){
          int zc = wN*32 + nb*8 + tig*2;
          z[zr*64 + zc]         = acc[mt2][nb][0];
          z[zr*64 + zc + 1]     = acc[mt2][nb][1];
          z[(zr+8)*64 + zc]     = acc[mt2][nb][2];
          z[(zr+8)*64 + zc + 1] = acc[mt2][nb][3];
        }
      }
    }
    __syncthreads();

    #pragma unroll
    for (int pi = 0; pi < 2; pi++){
      int p = tid + pi*256, r = p >> 4, c = p & 15;
      size_t rg = (size_t)t*128 + mbase + r;
      float zi = pz[pi][0], zf = pz[pi][1], zg = pz[pi][2], zo = pz[pi][3];
      #pragma unroll
      for (int k4 = 0; k4 < 4; k4++){
        const float* z = Zs + k4*(32*64) + r*64;
        zi += z[c]; zf += z[16 + c]; zg += z[32 + c]; zo += z[48 + c];
      }
      float cc = rc[pi] ? 0.f : cst[pi];
      float ig = 1.f/(1.f + __expf(-zi));
      float fg = 1.f/(1.f + __expf(-zf));
      float og = 1.f/(1.f + __expf(-zo));
      cc = fg*cc + ig*tanhf(zg);
      float nh = og*tanhf(cc);
      float nhr = tf(nh);
      cst[pi] = cc;
      int hcol = ni*16 + c;
      __stcg(&hn[((mbase+r)*4 + (c & 3))*128 + ni*4 + (c >> 2)], rn[pi] ? 0.f : nhr);
      ys[rg*512 + hcol] = (L == 0) ? nhr : nh;
      if (t == TT-1){
        coutP[(size_t)(mbase+r)*512 + hcol] = cc;
        houtP[(size_t)(mbase+r)*512 + hcol] = nh;
      }
    }
    gbar(mg);
  }
}

// ---------------- logits ----------------
__global__ __launch_bounds__(256) void logits_k(
    const float* __restrict__ W, const float* __restrict__ b, float* __restrict__ C)
{
  __shared__ float Ws[512*20];
  int tid = threadIdx.x;
  for (int i = tid; i < 512*20; i += 256) Ws[i] = W[i];
  __syncthreads();
  int row = blockIdx.x*8 + (tid >> 5), lane = tid & 31;
  float acc[20];
  #pragma unroll
  for (int c = 0; c < 20; c++) acc[c] = 0.f;
  #pragma unroll 4
  for (int j = 0; j < 16; j++){
    float a = g_hpre[(size_t)row*512 + lane + j*32];
    const float* w = &Ws[(lane + j*32)*20];
    #pragma unroll
    for (int c = 0; c < 20; c++) acc[c] += a*w[c];
  }
  #pragma unroll
  for (int c = 0; c < 20; c++)
    #pragma unroll
    for (int o = 16; o; o >>= 1) acc[c] += __shfl_xor_sync(0xffffffffu, acc[c], o);
  if (lane < 20) C[(size_t)row*20 + lane] = acc[lane] + b[lane];
}

// ---------------- launcher ----------------
extern "C" void kernel_launch(void* const* d_in, const int*, int, void* d_out_, int){
  const float* x     = (const float*)d_in[0];
  const void*  rsts  = d_in[1];
  const float* cc    = (const float*)d_in[2];
  const float* ch    = (const float*)d_in[3];
  const float* preW  = (const float*)d_in[4];
  const float* preb  = (const float*)d_in[5];
  const float* lns   = (const float*)d_in[6];
  const float* lnb   = (const float*)d_in[7];
  const float* Wi0   = (const float*)d_in[8];
  const float* Wh0   = (const float*)d_in[9];
  const float* b0    = (const float*)d_in[10];
  const float* Wi1   = (const float*)d_in[11];
  const float* Wh1   = (const float*)d_in[12];
  const float* b1    = (const float*)d_in[13];
  const float* postW = (const float*)d_in[14];
  const float* postb = (const float*)d_in[15];
  const float* outW  = (const float*)d_in[16];
  const float* outb  = (const float*)d_in[17];
  float* out = (float*)d_out_;
  const size_t OC = 0, OH = 131072, OL = 262144, OE = 1572864;

  cudaFuncSetAttribute(gemm_tf32<false,true>,  cudaFuncAttributeMaxDynamicSharedMemorySize, GEMM_SMEM);
  cudaFuncSetAttribute(gemm_tf32<false,false>, cudaFuncAttributeMaxDynamicSharedMemorySize, GEMM_SMEM);
  cudaFuncSetAttribute(gemm_tf32<true,true>,   cudaFuncAttributeMaxDynamicSharedMemorySize, GEMM_SMEM);
  cudaFuncSetAttribute(rec_lstm, cudaFuncAttributeMaxDynamicSharedMemorySize, RECSMEM);

  detect_resets<<<1,256>>>((const unsigned char*)rsts);
  conv_resets<<<256,256>>>(rsts);
  dim3 g512(4,512), g2048(16,512);

  pack_b<<<512,256>>>(preW, 512*512);
  gemm_tf32<false,true><<<g512,256,GEMM_SMEM>>>(x, 0, preb, 0, 512);
  ln_relu<<<8192,256>>>(lns, lnb);

  pack_b<<<2048,256>>>(Wi0, 512*2048);
  gemm_tf32<false,false><<<g2048,256,GEMM_SMEM>>>(nullptr, 1, b0, 0, 2048);
  pack_wh<<<2048,512>>>(Wh0, 0);
  init_rec<<<256,256>>>(ch);
  rec_lstm<<<128,256,RECSMEM>>>(0, cc, nullptr, out + OC, out + OH);

  pack_b<<<2048,256>>>(Wi1, 512*2048);
  gemm_tf32<false,false><<<g2048,256,GEMM_SMEM>>>(nullptr, 2, b1, 0, 2048);
  pack_wh<<<2048,512>>>(Wh1, 1);
  init_rec<<<256,256>>>(ch + 65536);
  rec_lstm<<<128,256,RECSMEM>>>(1, cc + 65536, out + OE,
                                out + OC + 65536, out + OH + 65536);

  pack_b<<<512,256>>>(postW, 512*512);
  gemm_tf32<true,true><<<g512,256,GEMM_SMEM>>>(out + OE, 0, postb, 1, 512);
  logits_k<<<8192,256>>>(outW, outb, out + OL);
}

// round 9
// speedup vs baseline: 1.8247x; 1.0960x over previous
#include <cuda_runtime.h>
#include <cuda_fp16.h>
#include <math.h>

#define TT 512
#define BB 128
#define HH 512
#define NZ 2048
#define TB 65536

// ---------------- static device scratch ----------------
__device__ float g_zx[(size_t)TB*NZ];
__device__ float g_hpre[(size_t)TB*HH];
__device__ float g_ys0[(size_t)TB*HH];
__device__ unsigned g_WhpU[2][(size_t)NZ*HH/2];  // half2: [(nc*4+p%4)*64 + p/4]
__device__ unsigned g_hbufU[2][BB*HH/2];         // half2: [(row*4+p%4)*64 + p/4]
__device__ float g_wBr[512*2048];                // pre-rounded B (stream-reused)
__device__ unsigned char g_rst[TB];
__device__ unsigned g_cnt[4], g_gen[4];
__device__ int g_rmode;

__device__ __forceinline__ float tf(float x){
  unsigned u; asm("cvt.rna.tf32.f32 %0,%1;" : "=r"(u) : "f"(x));
  return __uint_as_float(u);
}
__device__ __forceinline__ unsigned tfu(float x){
  unsigned u; asm("cvt.rna.tf32.f32 %0,%1;" : "=r"(u) : "f"(x));
  return u;
}
__device__ __forceinline__ void mma8(float* c, const unsigned* a, const unsigned* b){
  asm volatile("mma.sync.aligned.m16n8k8.row.col.f32.tf32.tf32.f32 "
    "{%0,%1,%2,%3},{%4,%5,%6,%7},{%8,%9},{%0,%1,%2,%3};"
    : "+f"(c[0]),"+f"(c[1]),"+f"(c[2]),"+f"(c[3])
    : "r"(a[0]),"r"(a[1]),"r"(a[2]),"r"(a[3]),"r"(b[0]),"r"(b[1]));
}
__device__ __forceinline__ void mma16(float* c, const unsigned* a, const unsigned* b){
  asm volatile("mma.sync.aligned.m16n8k16.row.col.f32.f16.f16.f32 "
    "{%0,%1,%2,%3},{%4,%5,%6,%7},{%8,%9},{%0,%1,%2,%3};"
    : "+f"(c[0]),"+f"(c[1]),"+f"(c[2]),"+f"(c[3])
    : "r"(a[0]),"r"(a[1]),"r"(a[2]),"r"(a[3]),"r"(b[0]),"r"(b[1]));
}
__device__ __forceinline__ void cpa16(void* dst, const void* src){
  unsigned d = (unsigned)__cvta_generic_to_shared(dst);
  asm volatile("cp.async.cg.shared.global [%0], [%1], 16;" :: "r"(d), "l"(src));
}
__device__ __forceinline__ float tanhx(float x){
  return 1.f - __fdividef(2.f, __expf(2.f*x) + 1.f);
}

// ---------------- resets dtype detect + convert ----------------
__global__ void detect_resets(const unsigned char* p){
  __shared__ int cF, c1;
  if (threadIdx.x == 0){ cF = 0; c1 = 0; }
  __syncthreads();
  for (int i = threadIdx.x; i < 65536; i += 256){
    unsigned char v = p[i];
    if (v == 0x3f || v == 0x80) atomicAdd(&cF, 1);
    else if (v == 1 && (i & 3)) atomicAdd(&c1, 1);
  }
  __syncthreads();
  if (threadIdx.x == 0) g_rmode = cF ? 2 : (c1 ? 1 : 0);
}
__global__ void conv_resets(const void* p){
  int i = blockIdx.x*blockDim.x + threadIdx.x;
  int m = g_rmode;
  bool z;
  if (m == 1)      z = ((const unsigned char*)p)[i] != 0;
  else if (m == 2) z = ((const float*)p)[i] != 0.f;
  else             z = ((const int*)p)[i] != 0;
  g_rst[i] = z ? 1 : 0;
}

// ---------------- weight pre-rounding (GEMM B, tf32) ----------------
__global__ void pack_b(const float* __restrict__ B, int n){
  for (int i = blockIdx.x*blockDim.x + threadIdx.x; i < n; i += gridDim.x*blockDim.x)
    g_wBr[i] = tf(B[i]);
}

// pack Wh[512][2048] -> fp16 pair-packed layout
__global__ void pack_wh(const float* __restrict__ Wh, int L){
  __half* dst = (__half*)g_WhpU[L];
  for (size_t idx = blockIdx.x*blockDim.x + threadIdx.x; idx < (size_t)HH*NZ;
       idx += (size_t)gridDim.x*blockDim.x){
    int k = idx >> 11, j = idx & (NZ-1);
    int g = j >> 9, r = j & 511;
    int nc = ((r >> 4) << 6) + (g << 4) + (r & 15);
    int p = k >> 1;
    dst[(((size_t)nc*4 + (p & 3))*64 + (p >> 2))*2 + (k & 1)] = __float2half(Wh[idx]);
  }
}

// init h buffer (fp16) with reset for t=0 pre-applied
__global__ void init_rec(const float* __restrict__ carryH){
  int i = blockIdx.x*blockDim.x + threadIdx.x;
  if (i < BB*HH){
    int row = i >> 9, col = i & 511;
    float v = g_rst[row] ? 0.f : carryH[i];
    int p = col >> 1;
    ((__half*)g_hbufU[0])[((row*4 + (p & 3))*64 + (p >> 2))*2 + (col & 1)] = __float2half(v);
  }
  if (i == 0){
    #pragma unroll
    for (int q = 0; q < 4; q++){ g_cnt[q] = 0u; g_gen[q] = 0u; }
  }
}

// ---------------- bulk tf32 GEMM (3-stage cp.async pipeline) ----------------
#define GEMM_SMEM (3*(128*36 + 32*136)*4)
#define AS(st,r,k) shA[((st)*128+(r))*36 + (k)]
#define BS(st,k,n) shB[((st)*32+(k))*136 + (n)]

template<bool RELU, bool CVTA>
__global__ __launch_bounds__(256) void gemm_tf32(
    const float* __restrict__ Aext, int aSel,
    const float* __restrict__ bias, int cSel, int N)
{
  extern __shared__ float sh[];
  float* shA = sh;
  float* shB = sh + 3*128*36;
  const float* A = (aSel == 1) ? g_hpre : (aSel == 2) ? g_ys0 : Aext;
  const float* B = g_wBr;
  float* C = (cSel == 1) ? g_hpre : g_zx;
  const int mt = blockIdx.y, nt = blockIdx.x, tid = threadIdx.x;
  const int wid = tid >> 5, lane = tid & 31, gID = lane >> 2, tig = lane & 3;
  const int wM = wid >> 1, wN = wid & 1;

  float acc[2][8][4];
  #pragma unroll
  for (int mi = 0; mi < 2; mi++)
    #pragma unroll
    for (int ni = 0; ni < 8; ni++)
      #pragma unroll
      for (int q = 0; q < 4; q++) acc[mi][ni][q] = 0.f;

  auto issue = [&](int kt, int st){
    #pragma unroll
    for (int i = 0; i < 4; i++){
      int idx = tid + i*256, r = idx >> 3, c4 = (idx & 7)*4;
      cpa16(&AS(st, r, c4), &A[(size_t)(mt*128 + r)*512 + kt*32 + c4]);
    }
    #pragma unroll
    for (int i = 0; i < 4; i++){
      int idx = tid + i*256, k = idx >> 5, n4 = (idx & 31)*4;
      cpa16(&BS(st, k, n4), &B[(size_t)(kt*32 + k)*N + nt*128 + n4]);
    }
    asm volatile("cp.async.commit_group;" ::: "memory");
  };

  issue(0, 0); issue(1, 1); issue(2, 2);
  int st = 0;
  for (int kt = 0; kt < 16; kt++){
    if (kt <= 13)      asm volatile("cp.async.wait_group 2;" ::: "memory");
    else if (kt == 14) asm volatile("cp.async.wait_group 1;" ::: "memory");
    else               asm volatile("cp.async.wait_group 0;" ::: "memory");
    __syncthreads();
    #pragma unroll
    for (int kk = 0; kk < 32; kk += 8){
      unsigned a[2][4], b[8][2];
      #pragma unroll
      for (int mi = 0; mi < 2; mi++){
        int r0 = wM*32 + mi*16 + gID;
        if (CVTA){
          a[mi][0] = tfu(AS(st, r0,   kk+tig));
          a[mi][1] = tfu(AS(st, r0+8, kk+tig));
          a[mi][2] = tfu(AS(st, r0,   kk+4+tig));
          a[mi][3] = tfu(AS(st, r0+8, kk+4+tig));
        } else {
          a[mi][0] = __float_as_uint(AS(st, r0,   kk+tig));
          a[mi][1] = __float_as_uint(AS(st, r0+8, kk+tig));
          a[mi][2] = __float_as_uint(AS(st, r0,   kk+4+tig));
          a[mi][3] = __float_as_uint(AS(st, r0+8, kk+4+tig));
        }
      }
      #pragma unroll
      for (int ni = 0; ni < 8; ni++){
        int n0 = wN*64 + ni*8 + gID;
        b[ni][0] = __float_as_uint(BS(st, kk+tig,   n0));
        b[ni][1] = __float_as_uint(BS(st, kk+4+tig, n0));
      }
      #pragma unroll
      for (int mi = 0; mi < 2; mi++)
        #pragma unroll
        for (int ni = 0; ni < 8; ni++)
          mma8(acc[mi][ni], a[mi], b[ni]);
    }
    __syncthreads();
    if (kt + 3 < 16) issue(kt + 3, st);
    st = (st == 2) ? 0 : st + 1;
  }

  #pragma unroll
  for (int mi = 0; mi < 2; mi++){
    int r0 = mt*128 + wM*32 + mi*16 + gID;
    #pragma unroll
    for (int ni = 0; ni < 8; ni++){
      int col = nt*128 + wN*64 + ni*8 + tig*2;
      float b0 = bias[col], b1 = bias[col+1];
      float v0 = acc[mi][ni][0]+b0, v1 = acc[mi][ni][1]+b1;
      float v2 = acc[mi][ni][2]+b0, v3 = acc[mi][ni][3]+b1;
      if (RELU){ v0=fmaxf(v0,0.f); v1=fmaxf(v1,0.f); v2=fmaxf(v2,0.f); v3=fmaxf(v3,0.f); }
      *(float2*)&C[(size_t)r0*N + col]     = make_float2(v0, v1);
      *(float2*)&C[(size_t)(r0+8)*N + col] = make_float2(v2, v3);
    }
  }
}

// ---------------- LayerNorm + ReLU (stores tf32-rounded) ----------------
__global__ __launch_bounds__(256) void ln_relu(
    const float* __restrict__ sc, const float* __restrict__ bi)
{
  int row = blockIdx.x*8 + (threadIdx.x >> 5), lane = threadIdx.x & 31;
  float v[16], s = 0.f, s2 = 0.f;
  #pragma unroll
  for (int j = 0; j < 16; j++){
    v[j] = g_zx[(size_t)row*512 + lane + j*32];
    s += v[j]; s2 += v[j]*v[j];
  }
  #pragma unroll
  for (int o = 16; o; o >>= 1){
    s  += __shfl_xor_sync(0xffffffffu, s,  o);
    s2 += __shfl_xor_sync(0xffffffffu, s2, o);
  }
  float mu = s*(1.f/512.f);
  float var = fmaxf(s2*(1.f/512.f) - mu*mu, 0.f);
  float rs = rsqrtf(var + 1e-6f);
  #pragma unroll
  for (int j = 0; j < 16; j++){
    int col = lane + j*32;
    g_hpre[(size_t)row*512 + col] = tf(fmaxf((v[j]-mu)*rs*sc[col] + bi[col], 0.f));
  }
}

// ---------------- persistent LSTM layer (fp16 operands) ----------------
// smem (uints): Bs 256x64 | As 128x64 | then Zs 4x32x64 floats
#define RECSMEM ((256*64 + 128*64)*4 + 4*32*64*4)

__device__ __forceinline__ void gbar(int mg){
  __syncthreads();
  if (threadIdx.x == 0){
    unsigned g0;
    asm volatile("ld.relaxed.gpu.global.u32 %0, [%1];"
                 : "=r"(g0) : "l"(&g_gen[mg]) : "memory");
    unsigned old;
    asm volatile("atom.add.release.gpu.global.u32 %0, [%1], %2;"
                 : "=r"(old) : "l"(&g_cnt[mg]), "r"(1u) : "memory");
    if (old == 31u){
      asm volatile("st.relaxed.gpu.global.u32 [%0], %1;"
                   :: "l"(&g_cnt[mg]), "r"(0u) : "memory");
      __threadfence();
      asm volatile("red.release.gpu.global.add.u32 [%0], %1;"
                   :: "l"(&g_gen[mg]), "r"(1u) : "memory");
    } else {
      unsigned g;
      do {
        asm volatile("ld.acquire.gpu.global.u32 %0, [%1];"
                     : "=r"(g) : "l"(&g_gen[mg]) : "memory");
      } while (g == g0);
    }
  }
  __syncthreads();
}

__global__ __launch_bounds__(256,1) void rec_lstm(
    int L, const float* __restrict__ carryC,
    float* __restrict__ ysExt, float* __restrict__ coutP, float* __restrict__ houtP)
{
  extern __shared__ unsigned smu[];
  unsigned* Bs2 = smu;                 // [256][64] half2, swizzled
  unsigned* As2 = smu + 256*64;        // [128][64] half2, swizzled
  float* Zs = (float*)(smu + 384*64);  // [4][32][64]

  const unsigned* WhpU = g_WhpU[L];
  float* ys = ysExt ? ysExt : g_ys0;
  const int tid = threadIdx.x, cta = blockIdx.x;
  const int mg = cta >> 5, mbase = mg*32, ni = cta & 31;
  const int wid = tid >> 5, lane = tid & 31, gID = lane >> 2, tig = lane & 3;
  const int wN = wid & 1, wK = wid >> 1;

  // resident Wh slice: 256 sub-rows x 64 uints
  for (int idx = tid; idx < 256*16; idx += 256){
    int r = idx >> 4, j4 = (idx & 15)*4;
    *(uint4*)&Bs2[r*64 + (j4 ^ ((r & 7) << 2))] =
      *(const uint4*)&WhpU[((size_t)ni*256 + r)*64 + j4];
  }
  float cst[2];
  #pragma unroll
  for (int pi = 0; pi < 2; pi++){
    int p = tid + pi*256, r = p >> 4, c = p & 15;
    cst[pi] = carryC[(size_t)(mbase+r)*512 + ni*16 + c];
  }

  int baseA[4], sA[4], baseB[4], sB[4];
  #pragma unroll
  for (int q = 0; q < 4; q++){
    int ra = (q*8 + gID)*4 + tig;
    int rb = (wN*32 + q*8 + gID)*4 + tig;
    baseA[q] = ra*64; sA[q] = (ra & 7) << 2;
    baseB[q] = rb*64; sB[q] = (rb & 7) << 2;
  }

  for (int t = 0; t < TT; t++){
    const unsigned* hb = g_hbufU[t & 1];
    __half* hn = (__half*)g_hbufU[(t & 1) ^ 1];

    // As fill: pure cp.async (h already reset-masked by producer), 8KB
    #pragma unroll
    for (int i = 0; i < 8; i++){
      int idx = tid + i*256;
      int r = idx >> 4, j4 = (idx & 15)*4;
      cpa16(&As2[r*64 + (j4 ^ ((r & 7) << 2))], &hb[(mbase*4 + r)*64 + j4]);
    }
    asm volatile("cp.async.commit_group;" ::: "memory");

    // prefetch Zx + resets into registers (overlaps cp.async)
    float pz[2][4]; int rc[2], rn[2];
    #pragma unroll
    for (int pi = 0; pi < 2; pi++){
      int p = tid + pi*256, r = p >> 4, c = p & 15;
      const float* zxr = &g_zx[((size_t)t*128 + mbase + r)*NZ + ni*16 + c];
      pz[pi][0] = __ldg(zxr);
      pz[pi][1] = __ldg(zxr + 512);
      pz[pi][2] = __ldg(zxr + 1024);
      pz[pi][3] = __ldg(zxr + 1536);
      rc[pi] = g_rst[t*128 + mbase + r];
      rn[pi] = (t == TT-1) ? 0 : g_rst[(t+1)*128 + mbase + r];
    }
    asm volatile("cp.async.wait_group 0;" ::: "memory");
    __syncthreads();

    {
      float acc[2][4][4];
      #pragma unroll
      for (int mt2 = 0; mt2 < 2; mt2++)
        #pragma unroll
        for (int nb = 0; nb < 4; nb++)
          #pragma unroll
          for (int q = 0; q < 4; q++) acc[mt2][nb][q] = 0.f;

      // 4 iterations: each uint4 = 4 half2 pairs = 2 x m16n8k16
      #pragma unroll
      for (int jj = 0; jj < 16; jj += 4){
        int j = wK*16 + jj;
        uint4 av[4], bv[4];
        #pragma unroll
        for (int q = 0; q < 4; q++)
          av[q] = *(const uint4*)&As2[baseA[q] + (j ^ sA[q])];
        #pragma unroll
        for (int q = 0; q < 4; q++)
          bv[q] = *(const uint4*)&Bs2[baseB[q] + (j ^ sB[q])];
        #pragma unroll
        for (int mt2 = 0; mt2 < 2; mt2++){
          unsigned Alo[4] = {av[2*mt2].x, av[2*mt2+1].x, av[2*mt2].y, av[2*mt2+1].y};
          unsigned Ahi[4] = {av[2*mt2].z, av[2*mt2+1].z, av[2*mt2].w, av[2*mt2+1].w};
          #pragma unroll
          for (int nb = 0; nb < 4; nb++){
            unsigned Blo[2] = {bv[nb].x, bv[nb].y};
            mma16(acc[mt2][nb], Alo, Blo);
            unsigned Bhi[2] = {bv[nb].z, bv[nb].w};
            mma16(acc[mt2][nb], Ahi, Bhi);
          }
        }
      }
      float* z = Zs + wK*(32*64);
      #pragma unroll
      for (int mt2 = 0; mt2 < 2; mt2++){
        int zr = mt2*16 + gID;
        #pragma unroll
        for (int nb = 0; nb < 4; nb++){
          int zc = wN*32 + nb*8 + tig*2;
          z[zr*64 + zc]         = acc[mt2][nb][0];
          z[zr*64 + zc + 1]     = acc[mt2][nb][1];
          z[(zr+8)*64 + zc]     = acc[mt2][nb][2];
          z[(zr+8)*64 + zc + 1] = acc[mt2][nb][3];
        }
      }
    }
    __syncthreads();

    #pragma unroll
    for (int pi = 0; pi < 2; pi++){
      int p = tid + pi*256, r = p >> 4, c = p & 15;
      size_t rg = (size_t)t*128 + mbase + r;
      float zi = pz[pi][0], zf = pz[pi][1], zg = pz[pi][2], zo = pz[pi][3];
      #pragma unroll
      for (int k4 = 0; k4 < 4; k4++){
        const float* z = Zs + k4*(32*64) + r*64;
        zi += z[c]; zf += z[16 + c]; zg += z[32 + c]; zo += z[48 + c];
      }
      float cc = rc[pi] ? 0.f : cst[pi];
      float ig = 1.f/(1.f + __expf(-zi));
      float fg = 1.f/(1.f + __expf(-zf));
      float og = 1.f/(1.f + __expf(-zo));
      cc = fg*cc + ig*tanhx(zg);
      float nh = og*tanhx(cc);
      cst[pi] = cc;
      int hcol = ni*16 + c;
      __half hh = __float2half(rn[pi] ? 0.f : nh);
      // pair up adjacent lanes (c even/odd) into one u32 store
      unsigned hu = (unsigned)__half_as_ushort(hh);
      unsigned hiu = __shfl_down_sync(0xffffffffu, hu, 1);
      if ((c & 1) == 0){
        int pp = hcol >> 1;
        unsigned* dst = (unsigned*)hn + (((mbase+r)*4 + (pp & 3))*64 + (pp >> 2));
        asm volatile("st.global.cg.u32 [%0], %1;" :: "l"(dst), "r"(hu | (hiu << 16)) : "memory");
      }
      ys[rg*512 + hcol] = (L == 0) ? __half2float(__float2half(nh)) : nh;
      if (t == TT-1){
        coutP[(size_t)(mbase+r)*512 + hcol] = cc;
        houtP[(size_t)(mbase+r)*512 + hcol] = nh;
      }
    }
    gbar(mg);
  }
}

// ---------------- logits ----------------
__global__ __launch_bounds__(256) void logits_k(
    const float* __restrict__ W, const float* __restrict__ b, float* __restrict__ C)
{
  __shared__ float Ws[512*20];
  int tid = threadIdx.x;
  for (int i = tid; i < 512*20; i += 256) Ws[i] = W[i];
  __syncthreads();
  int row = blockIdx.x*8 + (tid >> 5), lane = tid & 31;
  float acc[20];
  #pragma unroll
  for (int c = 0; c < 20; c++) acc[c] = 0.f;
  #pragma unroll 4
  for (int j = 0; j < 16; j++){
    float a = g_hpre[(size_t)row*512 + lane + j*32];
    const float* w = &Ws[(lane + j*32)*20];
    #pragma unroll
    for (int c = 0; c < 20; c++) acc[c] += a*w[c];
  }
  #pragma unroll
  for (int c = 0; c < 20; c++)
    #pragma unroll
    for (int o = 16; o; o >>= 1) acc[c] += __shfl_xor_sync(0xffffffffu, acc[c], o);
  if (lane < 20) C[(size_t)row*20 + lane] = acc[lane] + b[lane];
}

// ---------------- launcher ----------------
extern "C" void kernel_launch(void* const* d_in, const int*, int, void* d_out_, int){
  const float* x     = (const float*)d_in[0];
  const void*  rsts  = d_in[1];
  const float* cc    = (const float*)d_in[2];
  const float* ch    = (const float*)d_in[3];
  const float* preW  = (const float*)d_in[4];
  const float* preb  = (const float*)d_in[5];
  const float* lns   = (const float*)d_in[6];
  const float* lnb   = (const float*)d_in[7];
  const float* Wi0   = (const float*)d_in[8];
  const float* Wh0   = (const float*)d_in[9];
  const float* b0    = (const float*)d_in[10];
  const float* Wi1   = (const float*)d_in[11];
  const float* Wh1   = (const float*)d_in[12];
  const float* b1    = (const float*)d_in[13];
  const float* postW = (const float*)d_in[14];
  const float* postb = (const float*)d_in[15];
  const float* outW  = (const float*)d_in[16];
  const float* outb  = (const float*)d_in[17];
  float* out = (float*)d_out_;
  const size_t OC = 0, OH = 131072, OL = 262144, OE = 1572864;

  cudaFuncSetAttribute(gemm_tf32<false,true>,  cudaFuncAttributeMaxDynamicSharedMemorySize, GEMM_SMEM);
  cudaFuncSetAttribute(gemm_tf32<false,false>, cudaFuncAttributeMaxDynamicSharedMemorySize, GEMM_SMEM);
  cudaFuncSetAttribute(gemm_tf32<true,true>,   cudaFuncAttributeMaxDynamicSharedMemorySize, GEMM_SMEM);
  cudaFuncSetAttribute(rec_lstm, cudaFuncAttributeMaxDynamicSharedMemorySize, RECSMEM);

  detect_resets<<<1,256>>>((const unsigned char*)rsts);
  conv_resets<<<256,256>>>(rsts);
  dim3 g512(4,512), g2048(16,512);

  pack_b<<<512,256>>>(preW, 512*512);
  gemm_tf32<false,true><<<g512,256,GEMM_SMEM>>>(x, 0, preb, 0, 512);
  ln_relu<<<8192,256>>>(lns, lnb);

  pack_b<<<2048,256>>>(Wi0, 512*2048);
  gemm_tf32<false,false><<<g2048,256,GEMM_SMEM>>>(nullptr, 1, b0, 0, 2048);
  pack_wh<<<2048,512>>>(Wh0, 0);
  init_rec<<<256,256>>>(ch);
  rec_lstm<<<128,256,RECSMEM>>>(0, cc, nullptr, out + OC, out + OH);

  pack_b<<<2048,256>>>(Wi1, 512*2048);
  gemm_tf32<false,false><<<g2048,256,GEMM_SMEM>>>(nullptr, 2, b1, 0, 2048);
  pack_wh<<<2048,512>>>(Wh1, 1);
  init_rec<<<256,256>>>(ch + 65536);
  rec_lstm<<<128,256,RECSMEM>>>(1, cc + 65536, out + OE,
                                out + OC + 65536, out + OH + 65536);

  pack_b<<<512,256>>>(postW, 512*512);
  gemm_tf32<true,true><<<g512,256,GEMM_SMEM>>>(out + OE, 0, postb, 1, 512);
  logits_k<<<8192,256>>>(outW, outb, out + OL);
}

// round 10
// speedup vs baseline: 1.9527x; 1.0702x over previous
#include <cuda_runtime.h>
#include <cuda_fp16.h>
#include <math.h>

#define TT 512
#define BB 128
#define HH 512
#define NZ 2048
#define TB 65536

// ---------------- static device scratch ----------------
__device__ float g_zx[(size_t)TB*NZ];
__device__ float g_hpre[(size_t)TB*HH];          // post-GEMM fp32 out (logits in)
__device__ __half g_Ah[(size_t)TB*HH];           // fp16 GEMM A staging (reused)
__device__ __half g_wBh[2048*512];               // fp16 GEMM B, [n][k] transposed
__device__ unsigned g_WhpU[2][(size_t)NZ*HH/2];  // half2: [(nc*4+p%4)*64 + p/4]
__device__ unsigned g_hbufU[2][BB*HH/2];         // half2: [(row*4+p%4)*64 + p/4]
__device__ unsigned char g_rst[TB];
__device__ unsigned g_cnt[4], g_gen[4];
__device__ int g_rmode;

__device__ __forceinline__ void mma16(float* c, const unsigned* a, const unsigned* b){
  asm volatile("mma.sync.aligned.m16n8k16.row.col.f32.f16.f16.f32 "
    "{%0,%1,%2,%3},{%4,%5,%6,%7},{%8,%9},{%0,%1,%2,%3};"
    : "+f"(c[0]),"+f"(c[1]),"+f"(c[2]),"+f"(c[3])
    : "r"(a[0]),"r"(a[1]),"r"(a[2]),"r"(a[3]),"r"(b[0]),"r"(b[1]));
}
__device__ __forceinline__ void cpa16(void* dst, const void* src){
  unsigned d = (unsigned)__cvta_generic_to_shared(dst);
  asm volatile("cp.async.cg.shared.global [%0], [%1], 16;" :: "r"(d), "l"(src));
}
__device__ __forceinline__ float tanhx(float x){
  return 1.f - __fdividef(2.f, __expf(2.f*x) + 1.f);
}

// ---------------- resets dtype detect + convert ----------------
__global__ void detect_resets(const unsigned char* p){
  __shared__ int cF, c1;
  if (threadIdx.x == 0){ cF = 0; c1 = 0; }
  __syncthreads();
  for (int i = threadIdx.x; i < 65536; i += 256){
    unsigned char v = p[i];
    if (v == 0x3f || v == 0x80) atomicAdd(&cF, 1);
    else if (v == 1 && (i & 3)) atomicAdd(&c1, 1);
  }
  __syncthreads();
  if (threadIdx.x == 0) g_rmode = cF ? 2 : (c1 ? 1 : 0);
}
__global__ void conv_resets(const void* p){
  int i = blockIdx.x*blockDim.x + threadIdx.x;
  int m = g_rmode;
  bool z;
  if (m == 1)      z = ((const unsigned char*)p)[i] != 0;
  else if (m == 2) z = ((const float*)p)[i] != 0.f;
  else             z = ((const int*)p)[i] != 0;
  g_rst[i] = z ? 1 : 0;
}

// ---------------- fp32 -> fp16 A staging ----------------
__global__ void conv_x(const float* __restrict__ X, size_t n4){
  size_t i = (size_t)blockIdx.x*blockDim.x + threadIdx.x;
  if (i < n4){
    float4 v = *(const float4*)&X[i*4];
    unsigned lo = __half_as_ushort(__float2half(v.x)) |
                  ((unsigned)__half_as_ushort(__float2half(v.y)) << 16);
    unsigned hi = __half_as_ushort(__float2half(v.z)) |
                  ((unsigned)__half_as_ushort(__float2half(v.w)) << 16);
    ((uint2*)g_Ah)[i] = make_uint2(lo, hi);
  }
}

// ---------------- B transpose+convert: [k][N] f32 -> [n][512] f16 ----------
__global__ void pack_bh(const float* __restrict__ B, int N){
  __shared__ float t[32][33];
  int bx = blockIdx.x*32, by = blockIdx.y*32;   // bx: n-base, by: k-base
  int lx = threadIdx.x & 31, ly = threadIdx.x >> 5;
  #pragma unroll
  for (int q = 0; q < 32; q += 8)
    t[ly+q][lx] = B[(size_t)(by+ly+q)*N + bx+lx];
  __syncthreads();
  #pragma unroll
  for (int q = 0; q < 32; q += 8)
    g_wBh[(size_t)(bx+ly+q)*512 + by+lx] = __float2half(t[lx][ly+q]);
}

// pack Wh[512][2048] -> fp16 pair-packed layout
__global__ void pack_wh(const float* __restrict__ Wh, int L){
  __half* dst = (__half*)g_WhpU[L];
  for (size_t idx = blockIdx.x*blockDim.x + threadIdx.x; idx < (size_t)HH*NZ;
       idx += (size_t)gridDim.x*blockDim.x){
    int k = idx >> 11, j = idx & (NZ-1);
    int g = j >> 9, r = j & 511;
    int nc = ((r >> 4) << 6) + (g << 4) + (r & 15);
    int p = k >> 1;
    dst[(((size_t)nc*4 + (p & 3))*64 + (p >> 2))*2 + (k & 1)] = __float2half(Wh[idx]);
  }
}

// init h buffer (fp16) with reset for t=0 pre-applied
__global__ void init_rec(const float* __restrict__ carryH){
  int i = blockIdx.x*blockDim.x + threadIdx.x;
  if (i < BB*HH){
    int row = i >> 9, col = i & 511;
    float v = g_rst[row] ? 0.f : carryH[i];
    int p = col >> 1;
    ((__half*)g_hbufU[0])[((row*4 + (p & 3))*64 + (p >> 2))*2 + (col & 1)] = __float2half(v);
  }
  if (i == 0){
    #pragma unroll
    for (int q = 0; q < 4; q++){ g_cnt[q] = 0u; g_gen[q] = 0u; }
  }
}

// ---------------- bulk fp16 GEMM (3-stage cp.async, 2 CTA/SM) ----------------
// smem (uints): shA[3][128][20], shB[3][128][20]  (p = k/2; stride 20)
#define GS 20
#define GEMM_SMEM (2*3*128*GS*4)
#define HA(st,r,p) shA[((st)*128+(r))*GS + (p)]
#define HB(st,n,p) shB[((st)*128+(n))*GS + (p)]

template<bool RELU>
__global__ __launch_bounds__(256,2) void gemm_h(
    const float* __restrict__ bias, int cSel, int N)
{
  extern __shared__ unsigned shu[];
  unsigned* shA = shu;
  unsigned* shB = shu + 3*128*GS;
  float* C = (cSel == 1) ? g_hpre : g_zx;
  const int mt = blockIdx.y, nt = blockIdx.x, tid = threadIdx.x;
  const int wid = tid >> 5, lane = tid & 31, gID = lane >> 2, tig = lane & 3;
  const int wM = wid >> 1, wN = wid & 1;

  float acc[2][8][4];
  #pragma unroll
  for (int mi = 0; mi < 2; mi++)
    #pragma unroll
    for (int ni = 0; ni < 8; ni++)
      #pragma unroll
      for (int q = 0; q < 4; q++) acc[mi][ni][q] = 0.f;

  auto issue = [&](int kt, int st){
    #pragma unroll
    for (int i = 0; i < 2; i++){
      int c = tid + i*256, r = c >> 2, po = c & 3;
      cpa16(&HA(st, r, po*4), &g_Ah[(size_t)(mt*128 + r)*512 + kt*32 + po*8]);
    }
    #pragma unroll
    for (int i = 0; i < 2; i++){
      int c = tid + i*256, n = c >> 2, po = c & 3;
      cpa16(&HB(st, n, po*4), &g_wBh[(size_t)(nt*128 + n)*512 + kt*32 + po*8]);
    }
    asm volatile("cp.async.commit_group;" ::: "memory");
  };

  issue(0, 0); issue(1, 1); issue(2, 2);
  int st = 0;
  for (int kt = 0; kt < 16; kt++){
    if (kt <= 13)      asm volatile("cp.async.wait_group 2;" ::: "memory");
    else if (kt == 14) asm volatile("cp.async.wait_group 1;" ::: "memory");
    else               asm volatile("cp.async.wait_group 0;" ::: "memory");
    __syncthreads();
    #pragma unroll
    for (int kk = 0; kk < 2; kk++){
      int off = kk*8;
      unsigned a[2][4], b[8][2];
      #pragma unroll
      for (int mi = 0; mi < 2; mi++){
        int r0 = wM*32 + mi*16 + gID;
        a[mi][0] = HA(st, r0,   tig + off);
        a[mi][1] = HA(st, r0+8, tig + off);
        a[mi][2] = HA(st, r0,   tig + 4 + off);
        a[mi][3] = HA(st, r0+8, tig + 4 + off);
      }
      #pragma unroll
      for (int ni = 0; ni < 8; ni++){
        int n0 = wN*64 + ni*8 + gID;
        b[ni][0] = HB(st, n0, tig + off);
        b[ni][1] = HB(st, n0, tig + 4 + off);
      }
      #pragma unroll
      for (int mi = 0; mi < 2; mi++)
        #pragma unroll
        for (int ni = 0; ni < 8; ni++)
          mma16(acc[mi][ni], a[mi], b[ni]);
    }
    __syncthreads();
    if (kt + 3 < 16) issue(kt + 3, st);
    st = (st == 2) ? 0 : st + 1;
  }

  #pragma unroll
  for (int mi = 0; mi < 2; mi++){
    int r0 = mt*128 + wM*32 + mi*16 + gID;
    #pragma unroll
    for (int ni = 0; ni < 8; ni++){
      int col = nt*128 + wN*64 + ni*8 + tig*2;
      float b0 = bias[col], b1 = bias[col+1];
      float v0 = acc[mi][ni][0]+b0, v1 = acc[mi][ni][1]+b1;
      float v2 = acc[mi][ni][2]+b0, v3 = acc[mi][ni][3]+b1;
      if (RELU){ v0=fmaxf(v0,0.f); v1=fmaxf(v1,0.f); v2=fmaxf(v2,0.f); v3=fmaxf(v3,0.f); }
      *(float2*)&C[(size_t)r0*N + col]     = make_float2(v0, v1);
      *(float2*)&C[(size_t)(r0+8)*N + col] = make_float2(v2, v3);
    }
  }
}

// ---------------- LayerNorm + ReLU (fp32 in g_zx -> fp16 g_Ah) -------------
__global__ __launch_bounds__(256) void ln_relu(
    const float* __restrict__ sc, const float* __restrict__ bi)
{
  int row = blockIdx.x*8 + (threadIdx.x >> 5), lane = threadIdx.x & 31;
  float v[16], s = 0.f, s2 = 0.f;
  const float* src = &g_zx[(size_t)row*512 + lane*16];
  #pragma unroll
  for (int q = 0; q < 4; q++){
    float4 f = *(const float4*)&src[q*4];
    v[q*4]=f.x; v[q*4+1]=f.y; v[q*4+2]=f.z; v[q*4+3]=f.w;
    s += f.x+f.y+f.z+f.w;
    s2 += f.x*f.x+f.y*f.y+f.z*f.z+f.w*f.w;
  }
  #pragma unroll
  for (int o = 16; o; o >>= 1){
    s  += __shfl_xor_sync(0xffffffffu, s,  o);
    s2 += __shfl_xor_sync(0xffffffffu, s2, o);
  }
  float mu = s*(1.f/512.f);
  float var = fmaxf(s2*(1.f/512.f) - mu*mu, 0.f);
  float rs = rsqrtf(var + 1e-6f);
  unsigned* dst = (unsigned*)&g_Ah[(size_t)row*512 + lane*16];
  #pragma unroll
  for (int q = 0; q < 8; q++){
    int col = lane*16 + q*2;
    float y0 = fmaxf((v[q*2]  -mu)*rs*sc[col]   + bi[col],   0.f);
    float y1 = fmaxf((v[q*2+1]-mu)*rs*sc[col+1] + bi[col+1], 0.f);
    dst[q] = __half_as_ushort(__float2half(y0)) |
             ((unsigned)__half_as_ushort(__float2half(y1)) << 16);
  }
}

// ---------------- persistent LSTM layer (fp16 operands) ----------------
#define RECSMEM ((256*64 + 128*64)*4 + 4*32*64*4)

__device__ __forceinline__ void gbar(int mg){
  __syncthreads();
  if (threadIdx.x == 0){
    unsigned g0;
    asm volatile("ld.relaxed.gpu.global.u32 %0, [%1];"
                 : "=r"(g0) : "l"(&g_gen[mg]) : "memory");
    unsigned old;
    asm volatile("atom.add.release.gpu.global.u32 %0, [%1], %2;"
                 : "=r"(old) : "l"(&g_cnt[mg]), "r"(1u) : "memory");
    if (old == 31u){
      asm volatile("st.relaxed.gpu.global.u32 [%0], %1;"
                   :: "l"(&g_cnt[mg]), "r"(0u) : "memory");
      __threadfence();
      asm volatile("red.release.gpu.global.add.u32 [%0], %1;"
                   :: "l"(&g_gen[mg]), "r"(1u) : "memory");
    } else {
      unsigned g;
      do {
        asm volatile("ld.acquire.gpu.global.u32 %0, [%1];"
                     : "=r"(g) : "l"(&g_gen[mg]) : "memory");
      } while (g == g0);
    }
  }
  __syncthreads();
}

__global__ __launch_bounds__(256,1) void rec_lstm(
    int L, const float* __restrict__ carryC,
    float* __restrict__ emb, float* __restrict__ coutP, float* __restrict__ houtP)
{
  extern __shared__ unsigned smu[];
  unsigned* Bs2 = smu;                 // [256][64] half2, swizzled
  unsigned* As2 = smu + 256*64;        // [128][64] half2, swizzled
  float* Zs = (float*)(smu + 384*64);  // [4][32][64]

  const unsigned* WhpU = g_WhpU[L];
  const int tid = threadIdx.x, cta = blockIdx.x;
  const int mg = cta >> 5, mbase = mg*32, ni = cta & 31;
  const int wid = tid >> 5, lane = tid & 31, gID = lane >> 2, tig = lane & 3;
  const int wN = wid & 1, wK = wid >> 1;

  for (int idx = tid; idx < 256*16; idx += 256){
    int r = idx >> 4, j4 = (idx & 15)*4;
    *(uint4*)&Bs2[r*64 + (j4 ^ ((r & 7) << 2))] =
      *(const uint4*)&WhpU[((size_t)ni*256 + r)*64 + j4];
  }
  float cst[2];
  #pragma unroll
  for (int pi = 0; pi < 2; pi++){
    int p = tid + pi*256, r = p >> 4, c = p & 15;
    cst[pi] = carryC[(size_t)(mbase+r)*512 + ni*16 + c];
  }

  int baseA[4], sA[4], baseB[4], sB[4];
  #pragma unroll
  for (int q = 0; q < 4; q++){
    int ra = (q*8 + gID)*4 + tig;
    int rb = (wN*32 + q*8 + gID)*4 + tig;
    baseA[q] = ra*64; sA[q] = (ra & 7) << 2;
    baseB[q] = rb*64; sB[q] = (rb & 7) << 2;
  }

  for (int t = 0; t < TT; t++){
    const unsigned* hb = g_hbufU[t & 1];
    __half* hn = (__half*)g_hbufU[(t & 1) ^ 1];

    #pragma unroll
    for (int i = 0; i < 8; i++){
      int idx = tid + i*256;
      int r = idx >> 4, j4 = (idx & 15)*4;
      cpa16(&As2[r*64 + (j4 ^ ((r & 7) << 2))], &hb[(mbase*4 + r)*64 + j4]);
    }
    asm volatile("cp.async.commit_group;" ::: "memory");

    float pz[2][4]; int rc[2], rn[2];
    #pragma unroll
    for (int pi = 0; pi < 2; pi++){
      int p = tid + pi*256, r = p >> 4, c = p & 15;
      const float* zxr = &g_zx[((size_t)t*128 + mbase + r)*NZ + ni*16 + c];
      pz[pi][0] = __ldg(zxr);
      pz[pi][1] = __ldg(zxr + 512);
      pz[pi][2] = __ldg(zxr + 1024);
      pz[pi][3] = __ldg(zxr + 1536);
      rc[pi] = g_rst[t*128 + mbase + r];
      rn[pi] = (t == TT-1) ? 0 : g_rst[(t+1)*128 + mbase + r];
    }
    asm volatile("cp.async.wait_group 0;" ::: "memory");
    __syncthreads();

    {
      float acc[2][4][4];
      #pragma unroll
      for (int mt2 = 0; mt2 < 2; mt2++)
        #pragma unroll
        for (int nb = 0; nb < 4; nb++)
          #pragma unroll
          for (int q = 0; q < 4; q++) acc[mt2][nb][q] = 0.f;

      #pragma unroll
      for (int jj = 0; jj < 16; jj += 4){
        int j = wK*16 + jj;
        uint4 av[4], bv[4];
        #pragma unroll
        for (int q = 0; q < 4; q++)
          av[q] = *(const uint4*)&As2[baseA[q] + (j ^ sA[q])];
        #pragma unroll
        for (int q = 0; q < 4; q++)
          bv[q] = *(const uint4*)&Bs2[baseB[q] + (j ^ sB[q])];
        #pragma unroll
        for (int mt2 = 0; mt2 < 2; mt2++){
          unsigned Alo[4] = {av[2*mt2].x, av[2*mt2+1].x, av[2*mt2].y, av[2*mt2+1].y};
          unsigned Ahi[4] = {av[2*mt2].z, av[2*mt2+1].z, av[2*mt2].w, av[2*mt2+1].w};
          #pragma unroll
          for (int nb = 0; nb < 4; nb++){
            unsigned Blo[2] = {bv[nb].x, bv[nb].y};
            mma16(acc[mt2][nb], Alo, Blo);
            unsigned Bhi[2] = {bv[nb].z, bv[nb].w};
            mma16(acc[mt2][nb], Ahi, Bhi);
          }
        }
      }
      float* z = Zs + wK*(32*64);
      #pragma unroll
      for (int mt2 = 0; mt2 < 2; mt2++){
        int zr = mt2*16 + gID;
        #pragma unroll
        for (int nb = 0; nb < 4; nb++){
          int zc = wN*32 + nb*8 + tig*2;
          z[zr*64 + zc]         = acc[mt2][nb][0];
          z[zr*64 + zc + 1]     = acc[mt2][nb][1];
          z[(zr+8)*64 + zc]     = acc[mt2][nb][2];
          z[(zr+8)*64 + zc + 1] = acc[mt2][nb][3];
        }
      }
    }
    __syncthreads();

    #pragma unroll
    for (int pi = 0; pi < 2; pi++){
      int p = tid + pi*256, r = p >> 4, c = p & 15;
      size_t rg = (size_t)t*128 + mbase + r;
      float zi = pz[pi][0], zf = pz[pi][1], zg = pz[pi][2], zo = pz[pi][3];
      #pragma unroll
      for (int k4 = 0; k4 < 4; k4++){
        const float* z = Zs + k4*(32*64) + r*64;
        zi += z[c]; zf += z[16 + c]; zg += z[32 + c]; zo += z[48 + c];
      }
      float cc = rc[pi] ? 0.f : cst[pi];
      float ig = 1.f/(1.f + __expf(-zi));
      float fg = 1.f/(1.f + __expf(-zf));
      float og = 1.f/(1.f + __expf(-zo));
      cc = fg*cc + ig*tanhx(zg);
      float nh = og*tanhx(cc);
      cst[pi] = cc;
      int hcol = ni*16 + c;

      unsigned yu = (unsigned)__half_as_ushort(__float2half(nh));
      unsigned yhi = __shfl_down_sync(0xffffffffu, yu, 1);
      unsigned hu = rn[pi] ? 0u : yu;
      unsigned hhi = __shfl_down_sync(0xffffffffu, hu, 1);
      if ((c & 1) == 0){
        int pp = hcol >> 1;
        unsigned* hd = (unsigned*)hn + (((mbase+r)*4 + (pp & 3))*64 + (pp >> 2));
        asm volatile("st.global.cg.u32 [%0], %1;" :: "l"(hd), "r"(hu | (hhi << 16)) : "memory");
        unsigned* yd = (unsigned*)g_Ah + ((rg*512 + hcol) >> 1);
        asm volatile("st.global.cg.u32 [%0], %1;" :: "l"(yd), "r"(yu | (yhi << 16)) : "memory");
      }
      if (emb) emb[rg*512 + hcol] = nh;
      if (t == TT-1){
        coutP[(size_t)(mbase+r)*512 + hcol] = cc;
        houtP[(size_t)(mbase+r)*512 + hcol] = nh;
      }
    }
    gbar(mg);
  }
}

// ---------------- logits ----------------
__global__ __launch_bounds__(256) void logits_k(
    const float* __restrict__ W, const float* __restrict__ b, float* __restrict__ C)
{
  __shared__ float Ws[512*20];
  int tid = threadIdx.x;
  for (int i = tid; i < 512*20; i += 256) Ws[i] = W[i];
  __syncthreads();
  int row = blockIdx.x*8 + (tid >> 5), lane = tid & 31;
  float acc[20];
  #pragma unroll
  for (int c = 0; c < 20; c++) acc[c] = 0.f;
  #pragma unroll 4
  for (int j = 0; j < 16; j++){
    float a = g_hpre[(size_t)row*512 + lane + j*32];
    const float* w = &Ws[(lane + j*32)*20];
    #pragma unroll
    for (int c = 0; c < 20; c++) acc[c] += a*w[c];
  }
  #pragma unroll
  for (int c = 0; c < 20; c++)
    #pragma unroll
    for (int o = 16; o; o >>= 1) acc[c] += __shfl_xor_sync(0xffffffffu, acc[c], o);
  if (lane < 20) C[(size_t)row*20 + lane] = acc[lane] + b[lane];
}

// ---------------- launcher ----------------
extern "C" void kernel_launch(void* const* d_in, const int*, int, void* d_out_, int){
  const float* x     = (const float*)d_in[0];
  const void*  rsts  = d_in[1];
  const float* cc    = (const float*)d_in[2];
  const float* ch    = (const float*)d_in[3];
  const float* preW  = (const float*)d_in[4];
  const float* preb  = (const float*)d_in[5];
  const float* lns   = (const float*)d_in[6];
  const float* lnb   = (const float*)d_in[7];
  const float* Wi0   = (const float*)d_in[8];
  const float* Wh0   = (const float*)d_in[9];
  const float* b0    = (const float*)d_in[10];
  const float* Wi1   = (const float*)d_in[11];
  const float* Wh1   = (const float*)d_in[12];
  const float* b1    = (const float*)d_in[13];
  const float* postW = (const float*)d_in[14];
  const float* postb = (const float*)d_in[15];
  const float* outW  = (const float*)d_in[16];
  const float* outb  = (const float*)d_in[17];
  float* out = (float*)d_out_;
  const size_t OC = 0, OH = 131072, OL = 262144, OE = 1572864;

  cudaFuncSetAttribute(gemm_h<false>, cudaFuncAttributeMaxDynamicSharedMemorySize, GEMM_SMEM);
  cudaFuncSetAttribute(gemm_h<true>,  cudaFuncAttributeMaxDynamicSharedMemorySize, GEMM_SMEM);
  cudaFuncSetAttribute(rec_lstm, cudaFuncAttributeMaxDynamicSharedMemorySize, RECSMEM);

  detect_resets<<<1,256>>>((const unsigned char*)rsts);
  conv_resets<<<256,256>>>(rsts);
  dim3 g512(4,512), g2048(16,512);
  dim3 tp512(16,16), tp2048(64,16);

  conv_x<<<32768,256>>>(x, (size_t)TB*HH/4);
  pack_bh<<<tp512,256>>>(preW, 512);
  gemm_h<false><<<g512,256,GEMM_SMEM>>>(preb, 0, 512);
  ln_relu<<<8192,256>>>(lns, lnb);

  pack_bh<<<tp2048,256>>>(Wi0, 2048);
  gemm_h<false><<<g2048,256,GEMM_SMEM>>>(b0, 0, 2048);
  pack_wh<<<2048,512>>>(Wh0, 0);
  init_rec<<<256,256>>>(ch);
  rec_lstm<<<128,256,RECSMEM>>>(0, cc, nullptr, out + OC, out + OH);

  pack_bh<<<tp2048,256>>>(Wi1, 2048);
  gemm_h<false><<<g2048,256,GEMM_SMEM>>>(b1, 0, 2048);
  pack_wh<<<2048,512>>>(Wh1, 1);
  init_rec<<<256,256>>>(ch + 65536);
  rec_lstm<<<128,256,RECSMEM>>>(1, cc + 65536, out + OE,
                                out + OC + 65536, out + OH + 65536);

  pack_bh<<<tp512,256>>>(postW, 512);
  gemm_h<true><<<g512,256,GEMM_SMEM>>>(postb, 1, 512);
  logits_k<<<8192,256>>>(outW, outb, out + OL);
}